// round 9
// baseline (speedup 1.0000x reference)
#include <cuda_runtime.h>
#include <cstdint>

#define H 1024
#define W 1024
#define D 128
#define K 2048
#define NCAP (1 << 20)
#define SELCAP 4096
#define NB 128            // blocks; <= 148 SMs so all co-resident
#define NT 1024
#define NH 8              // replicated hist1 copies
#define NEG_INF __int_as_float(0xFF800000)

// Output layout (float32): keypoints[K,2] | scores[K] | d[K,D] | valid[K]
#define OUT_KP 0
#define OUT_SC (K * 2)
#define OUT_D (K * 2 + K)
#define OUT_VALID (K * 2 + K + K * D)

// ---------------- scratch (static device globals; no allocation) ----------------
__device__ unsigned long long g_cand[NCAP];
__device__ unsigned long long g_sel[SELCAP];
__device__ int g_ncand;
__device__ int g_nsel;
__device__ unsigned int g_hist1[NH][2048];
__device__ unsigned int g_hist2[2048];
__device__ unsigned int g_barcnt;
__device__ volatile unsigned int g_bargen;
__device__ unsigned int g_done;

// ---------------- shared memory union (per-phase reuse) ----------------
struct ScanSm { unsigned int s[2048]; };
struct RankSm { unsigned long long keys[SELCAP]; };
union SmU { ScanSm scan; RankSm rank; };

// ---------------- software grid barrier (all NB blocks resident) ----------------
__device__ __forceinline__ void gbar() {
    __syncthreads();
    if (threadIdx.x == 0) {
        unsigned int gen = g_bargen;
        __threadfence();
        if (atomicAdd(&g_barcnt, 1u) == NB - 1) {
            g_barcnt = 0;
            __threadfence();
            g_bargen = gen + 1;
        } else {
            while (g_bargen == gen) { }
        }
        __threadfence();
    }
    __syncthreads();
}

__device__ __forceinline__ void suffix_scan_2048(unsigned int* s, int tid) {
    for (int off = 1; off < 2048; off <<= 1) {
        unsigned int a0 = (tid + off < 2048) ? s[tid + off] : 0u;
        unsigned int a1 = (tid + 1024 + off < 2048) ? s[tid + 1024 + off] : 0u;
        __syncthreads();
        s[tid] += a0;
        s[tid + 1024] += a1;
        __syncthreads();
    }
}

__global__ __launch_bounds__(NT, 1) void disk_mega(const float* __restrict__ feat,
                                                   const int* __restrict__ ow_p,
                                                   const int* __restrict__ oh_p,
                                                   float* __restrict__ out) {
    __shared__ SmU sm;
    __shared__ unsigned int sb1, sabove1, stmin;
    __shared__ int slast;
    const unsigned int F = 0xFFFFFFFFu;
    const int tid = threadIdx.x;
    const int gid = blockIdx.x * NT + tid;
    const int lane = tid & 31;
    const int wid = tid >> 5;
    const float* heat = feat + (size_t)D * H * W;
    const int ow = ow_p ? __ldg(ow_p) : W;
    const int oh = oh_p ? __ldg(oh_p) : H;

    // ========== phase 1: warp-rolling NMS detect (no smem, no syncs) ============
    // One warp per 32-col x 8-row patch: 32 strips x 128 chunks = 4096 warp-tasks.
    {
        const int tw = blockIdx.x * 32 + wid;      // 0..4095
        const int strip = tw & 31;
        const int chunk = tw >> 5;
        const int x = strip * 32 + lane;
        const int y0 = chunk * 8;
        const int hc = blockIdx.x & (NH - 1);

        // load 12 rows of own column (coalesced, MLP=12)
        float v[12];
#pragma unroll
        for (int r = 0; r < 12; r++) {
            const int yr = y0 - 2 + r;
            v[r] = (yr >= 0 && yr < H) ? __ldg(&heat[(size_t)yr * W + x]) : NEG_INF;
        }
        // horizontal 5-max per row via shuffles + edge halo loads
        const int ex = (lane < 2) ? x - 2 : x + 2;
        const bool edge = (lane < 2) || (lane > 29);
        const int esrc = (lane == 0) ? 1 : 30;     // cross-halo partner lane
        float hm[12];
#pragma unroll
        for (int r = 0; r < 12; r++) {
            const int yr = y0 - 2 + r;
            float e = NEG_INF;
            if (edge && yr >= 0 && yr < H && ex >= 0 && ex < W)
                e = __ldg(&heat[(size_t)yr * W + ex]);
            float a = __shfl_up_sync(F, v[r], 2);
            float b = __shfl_up_sync(F, v[r], 1);
            float d = __shfl_down_sync(F, v[r], 1);
            float g = __shfl_down_sync(F, v[r], 2);
            const float eo = __shfl_sync(F, e, esrc);
            if (lane == 0) { a = e; b = eo; }
            if (lane == 1) { a = e; }
            if (lane == 30) { g = e; }
            if (lane == 31) { g = e; d = eo; }
            hm[r] = fmaxf(fmaxf(fmaxf(a, b), fmaxf(v[r], d)), g);
        }
        // vertical 5-max + candidate predicate per output row
        unsigned int mk[8];
        unsigned int pr = 0;
#pragma unroll
        for (int k = 0; k < 8; k++) {
            const float c = v[k + 2];
            const float m = fmaxf(fmaxf(fmaxf(hm[k], hm[k + 1]),
                                        fmaxf(hm[k + 2], hm[k + 3])),
                                  hm[k + 4]);
            const bool pred = (c > 0.0f) && (c == m) && (x <= ow - 1) &&
                              ((y0 + k) <= oh - 1);
            mk[k] = __ballot_sync(F, pred);
            pr |= pred ? (1u << k) : 0u;
        }
        int total = 0;
#pragma unroll
        for (int k = 0; k < 8; k++) total += __popc(mk[k]);
        if (total) {
            int base = 0;
            if (lane == 0) base = atomicAdd(&g_ncand, total);
            base = __shfl_sync(F, base, 0);
            int run = 0;
#pragma unroll
            for (int k = 0; k < 8; k++) {
                if (pr & (1u << k)) {
                    const int off = run + __popc(mk[k] & ((1u << lane) - 1u));
                    const float c = v[k + 2];
                    const unsigned int uk = __float_as_uint(c) | 0x80000000u;
                    const unsigned int idx = (unsigned int)((y0 + k) * W + x);
                    g_cand[base + off] =
                        ((unsigned long long)uk << 32) | (0xFFFFFFFFu - idx);
                    atomicAdd(&g_hist1[hc][uk >> 21], 1u);
                }
                run += __popc(mk[k]);
            }
        }
    }
    gbar();

    // ========== phase 2: redundant per-block scan1 -> b1; then hist2 ============
    {
        unsigned int a0 = 0u, a1 = 0u;
#pragma unroll
        for (int c = 0; c < NH; c++) {
            a0 += __ldcg(&g_hist1[c][tid]);
            a1 += __ldcg(&g_hist1[c][tid + 1024]);
        }
        sm.scan.s[tid] = a0;
        sm.scan.s[tid + 1024] = a1;
        __syncthreads();
        suffix_scan_2048(sm.scan.s, tid);
        for (int b = tid; b < 2048; b += NT) {
            if (sm.scan.s[b] >= K && (b == 2047 || sm.scan.s[b + 1] < K)) {
                sb1 = (unsigned int)b;
                sabove1 = (b < 2047) ? sm.scan.s[b + 1] : 0u;
            }
        }
        if (tid == 0 && sm.scan.s[0] < K) { sb1 = 0u; sabove1 = 0u; }
        __syncthreads();
        const unsigned int b1 = sb1;
        const int n = min(__ldcg(&g_ncand), NCAP);
        for (int i = gid; i < n; i += NB * NT) {
            const unsigned int hi = (unsigned int)(__ldcg(&g_cand[i]) >> 32);
            if ((hi >> 21) == b1) atomicAdd(&g_hist2[(hi >> 10) & 0x7FFu], 1u);
        }
    }
    gbar();

    // ========== phase 3: redundant per-block scan2 -> tmin; then compact ========
    {
        const unsigned int above1 = sabove1;   // survives in shared across gbar
        const unsigned int b1 = sb1;
        sm.scan.s[tid] = __ldcg(&g_hist2[tid]);
        sm.scan.s[tid + 1024] = __ldcg(&g_hist2[tid + 1024]);
        __syncthreads();
        suffix_scan_2048(sm.scan.s, tid);
        for (int b = tid; b < 2048; b += NT) {
            if (above1 + sm.scan.s[b] >= K &&
                (b == 2047 || above1 + sm.scan.s[b + 1] < K)) {
                stmin = (b1 << 21) | ((unsigned int)b << 10);
            }
        }
        if (tid == 0 && above1 + sm.scan.s[0] < K) stmin = (b1 << 21);
        __syncthreads();
        const unsigned int tmin = stmin;
        const int n = min(__ldcg(&g_ncand), NCAP);
        const int stride = NB * NT;
        const int niter = (n + stride - 1) / stride;   // UNIFORM trip count
        for (int t = 0; t < niter; t++) {
            const int i = gid + t * stride;
            unsigned long long key = 0ull;
            bool keep = false;
            if (i < n) {
                key = __ldcg(&g_cand[i]);
                keep = ((unsigned int)(key >> 32)) >= tmin;
            }
            const unsigned int mask = __ballot_sync(F, keep);
            if (mask) {
                const int leader = __ffs(mask) - 1;
                int base = 0;
                if (lane == leader) base = atomicAdd(&g_nsel, __popc(mask));
                base = __shfl_sync(F, base, leader);
                if (keep) {
                    const int off = __popc(mask & ((1u << lane) - 1u));
                    if (base + off < SELCAP) g_sel[base + off] = key;
                }
            }
        }
    }
    gbar();

    // ========== phase 4: rank (one warp/survivor) + emit + fused gather =========
    {
        const int nsel = min(__ldcg(&g_nsel), SELCAP);
        for (int i = tid; i < nsel; i += NT) sm.rank.keys[i] = __ldcg(&g_sel[i]);
        __syncthreads();
        const int gi = wid * NB + blockIdx.x;  // strided: spreads gather over blocks
        if (gi < nsel) {
            const unsigned long long key = sm.rank.keys[gi];
            unsigned int r = 0;
            for (int j = lane; j < nsel; j += 32)
                r += (sm.rank.keys[j] > key) ? 1u : 0u;
            r = __reduce_add_sync(F, r);   // exact rank, keys unique
            if (r < K) {
                const unsigned int hi = (unsigned int)(key >> 32);
                const unsigned int idx = 0xFFFFFFFFu - (unsigned int)key;
                if (lane == 0) {
                    out[OUT_KP + 2 * r + 0] = (float)(idx & (W - 1));
                    out[OUT_KP + 2 * r + 1] = (float)(idx >> 10);
                    out[OUT_SC + r] = __uint_as_float(hi & 0x7FFFFFFFu);
                    out[OUT_VALID + r] = 1.0f;
                }
                // fused descriptor gather + L2 normalize (4 channels per lane)
                float v0 = __ldg(&feat[(size_t)(lane)*(H * W) + idx]);
                float v1 = __ldg(&feat[(size_t)(lane + 32) * (H * W) + idx]);
                float v2 = __ldg(&feat[(size_t)(lane + 64) * (H * W) + idx]);
                float v3 = __ldg(&feat[(size_t)(lane + 96) * (H * W) + idx]);
                float ss = v0 * v0 + v1 * v1 + v2 * v2 + v3 * v3;
#pragma unroll
                for (int o = 16; o > 0; o >>= 1)
                    ss += __shfl_xor_sync(F, ss, o);
                const float inorm = 1.0f / fmaxf(sqrtf(ss), 1e-12f);
                float* drow = out + OUT_D + (size_t)r * D;
                drow[lane] = v0 * inorm;
                drow[lane + 32] = v1 * inorm;
                drow[lane + 64] = v2 * inorm;
                drow[lane + 96] = v3 * inorm;
            }
        } else if (gi < K) {  // padding rows when nsel < K (rows nsel..K-1)
            if (lane == 0) {
                out[OUT_KP + 2 * gi + 0] = 0.0f;
                out[OUT_KP + 2 * gi + 1] = 0.0f;
                out[OUT_SC + gi] = NEG_INF;
                out[OUT_VALID + gi] = 0.0f;
            }
            float* drow = out + OUT_D + (size_t)gi * D;
            drow[lane] = 0.0f;
            drow[lane + 32] = 0.0f;
            drow[lane + 64] = 0.0f;
            drow[lane + 96] = 0.0f;
        }
    }

    // ========== tail: last block to finish re-zeros ALL state for next replay ===
    __syncthreads();
    if (tid == 0) {
        __threadfence();
        slast = (atomicAdd(&g_done, 1u) == NB - 1) ? 1 : 0;
    }
    __syncthreads();
    if (slast) {
        unsigned int* h1 = &g_hist1[0][0];
        for (int i = tid; i < NH * 2048; i += NT) h1[i] = 0u;
        for (int i = tid; i < 2048; i += NT) g_hist2[i] = 0u;
        __syncthreads();
        if (tid == 0) { g_ncand = 0; g_nsel = 0; __threadfence(); g_done = 0u; }
    }
}

// ---------------- launch ---------------------------------------------------------
extern "C" void kernel_launch(void* const* d_in, const int* in_sizes, int n_in,
                              void* d_out, int out_size) {
    const float* feat = (const float*)d_in[0];
    const int* ow_p = (n_in > 1) ? (const int*)d_in[1] : nullptr;
    const int* oh_p = (n_in > 2) ? (const int*)d_in[2] : nullptr;
    float* out = (float*)d_out;
    disk_mega<<<NB, NT>>>(feat, ow_p, oh_p, out);
}

// round 10
// speedup vs baseline: 1.0529x; 1.0529x over previous
#include <cuda_runtime.h>
#include <cstdint>

#define H 1024
#define W 1024
#define D 128
#define K 2048
#define NCAP (1 << 20)
#define SELCAP 4096
#define NB 128            // blocks; <= 148 SMs so all co-resident
#define NT 1024
#define NH 8              // replicated hist1 copies
#define NEG_INF __int_as_float(0xFF800000)

// Output layout (float32): keypoints[K,2] | scores[K] | d[K,D] | valid[K]
#define OUT_KP 0
#define OUT_SC (K * 2)
#define OUT_D (K * 2 + K)
#define OUT_VALID (K * 2 + K + K * D)

// ---------------- scratch (static device globals; no allocation) ----------------
__device__ unsigned long long g_cand[NCAP];
__device__ unsigned long long g_sel[SELCAP];
__device__ int g_ncand;
__device__ int g_nsel;
__device__ unsigned int g_hist1[NH][2048];
__device__ unsigned int g_hist2[2048];
__device__ unsigned int g_barcnt;
__device__ volatile unsigned int g_bargen;
__device__ unsigned int g_done;

// ---------------- shared memory union (per-phase reuse) ----------------
struct __align__(16) DetSm {
    float tile[36][44];     // halo cols [bx-4, bx+36)
    float rowmax[36][33];
};
struct ScanSm { unsigned int s[2048]; };
struct RankSm { unsigned long long keys[SELCAP]; };
union SmU { DetSm det; ScanSm scan; RankSm rank; };

// ---------------- software grid barrier (all NB blocks resident) ----------------
__device__ __forceinline__ void gbar() {
    __syncthreads();
    if (threadIdx.x == 0) {
        unsigned int gen = g_bargen;
        __threadfence();
        if (atomicAdd(&g_barcnt, 1u) == NB - 1) {
            g_barcnt = 0;
            __threadfence();
            g_bargen = gen + 1;
        } else {
            while (g_bargen == gen) { }
        }
        __threadfence();
    }
    __syncthreads();
}

__device__ __forceinline__ void suffix_scan_2048(unsigned int* s, int tid) {
    for (int off = 1; off < 2048; off <<= 1) {
        unsigned int a0 = (tid + off < 2048) ? s[tid + off] : 0u;
        unsigned int a1 = (tid + 1024 + off < 2048) ? s[tid + 1024 + off] : 0u;
        __syncthreads();
        s[tid] += a0;
        s[tid + 1024] += a1;
        __syncthreads();
    }
}

__global__ __launch_bounds__(NT, 1) void disk_mega(const float* __restrict__ feat,
                                                   const int* __restrict__ ow_p,
                                                   const int* __restrict__ oh_p,
                                                   float* __restrict__ out) {
    __shared__ SmU sm;
    __shared__ unsigned int sb1, sabove1, scnt1, stmin;
    __shared__ int slast;
    const unsigned int F = 0xFFFFFFFFu;
    const int tid = threadIdx.x;
    const int gid = blockIdx.x * NT + tid;
    const int lane = tid & 31;
    const int wid = tid >> 5;
    const float* heat = feat + (size_t)D * H * W;
    const int ow = ow_p ? __ldg(ow_p) : W;
    const int oh = oh_p ? __ldg(oh_p) : H;

    // ========== phase 1: tiled NMS detect with register-prefetch pipeline =======
    {
        const int lx = lane, ly = wid;           // 32x32 tile, warp = row
        const int hc = blockIdx.x & (NH - 1);
        const int hr = tid / 10, hx = tid - hr * 10;   // halo loader coords (tid<360)
        int t = blockIdx.x;

        // prefetch tile 0 halo into registers
        float4 hv = make_float4(NEG_INF, NEG_INF, NEG_INF, NEG_INF);
        if (tid < 360) {
            const int bx = (t & 31) * 32, by = (t >> 5) * 32;
            const int gy = by - 2 + hr, gx0 = bx - 4 + hx * 4;
            if (gy >= 0 && gy < H && gx0 >= 0 && gx0 < W)
                hv = *(const float4*)(heat + (size_t)gy * W + gx0);
        }

        for (int it = 0; it < 8; it++) {
            const int bx = (t & 31) * 32, by = (t >> 5) * 32;
            if (tid < 360) *(float4*)&sm.det.tile[hr][hx * 4] = hv;
            __syncthreads();
            // kick off next tile's halo loads (overlaps with compute below)
            if (it < 7) {
                float4 nv = make_float4(NEG_INF, NEG_INF, NEG_INF, NEG_INF);
                if (tid < 360) {
                    const int tn = t + NB;
                    const int nbx = (tn & 31) * 32, nby = (tn >> 5) * 32;
                    const int gy = nby - 2 + hr, gx0 = nbx - 4 + hx * 4;
                    if (gy >= 0 && gy < H && gx0 >= 0 && gx0 < W)
                        nv = *(const float4*)(heat + (size_t)gy * W + gx0);
                }
                hv = nv;
            }
            // horizontal 5-max
            for (int i = tid; i < 36 * 32; i += NT) {
                const int ty = i >> 5, tx = i & 31;
                const float* row = sm.det.tile[ty];
                sm.det.rowmax[ty][tx] =
                    fmaxf(fmaxf(fmaxf(row[tx + 2], row[tx + 3]),
                                fmaxf(row[tx + 4], row[tx + 5])),
                          row[tx + 6]);
            }
            __syncthreads();
            // vertical 5-max + warp-aggregated candidate emission
            const float v = sm.det.tile[ly + 2][lx + 4];
            const float m =
                fmaxf(fmaxf(fmaxf(sm.det.rowmax[ly][lx], sm.det.rowmax[ly + 1][lx]),
                            fmaxf(sm.det.rowmax[ly + 2][lx], sm.det.rowmax[ly + 3][lx])),
                      sm.det.rowmax[ly + 4][lx]);
            const int x = bx + lx, y = by + ly;
            const bool pred = (v > 0.0f) && (v == m) && (x <= ow - 1) && (y <= oh - 1);
            const unsigned int mask = __ballot_sync(F, pred);
            if (mask) {
                int base = 0;
                if (lane == 0) base = atomicAdd(&g_ncand, __popc(mask));
                base = __shfl_sync(F, base, 0);
                if (pred) {
                    const unsigned int uk = __float_as_uint(v) | 0x80000000u;
                    const unsigned int idx = (unsigned int)(y * W + x);
                    g_cand[base + __popc(mask & ((1u << lane) - 1u))] =
                        ((unsigned long long)uk << 32) | (0xFFFFFFFFu - idx);
                    atomicAdd(&g_hist1[hc][uk >> 21], 1u);
                }
            }
            __syncthreads();   // before overwriting tile next iteration
            t += NB;
        }
    }
    gbar();

    // ========== phase 2: scan1 -> b1; fast-path threshold or level-2 refine =====
    unsigned int tmin;
    {
        unsigned int a0 = 0u, a1 = 0u;
#pragma unroll
        for (int c = 0; c < NH; c++) {
            a0 += __ldcg(&g_hist1[c][tid]);
            a1 += __ldcg(&g_hist1[c][tid + 1024]);
        }
        sm.scan.s[tid] = a0;
        sm.scan.s[tid + 1024] = a1;
        __syncthreads();
        suffix_scan_2048(sm.scan.s, tid);
        for (int b = tid; b < 2048; b += NT) {
            if (sm.scan.s[b] >= K && (b == 2047 || sm.scan.s[b + 1] < K)) {
                sb1 = (unsigned int)b;
                sabove1 = (b < 2047) ? sm.scan.s[b + 1] : 0u;
                scnt1 = sm.scan.s[b];
            }
        }
        if (tid == 0 && sm.scan.s[0] < K) { sb1 = 0u; sabove1 = 0u; scnt1 = sm.scan.s[0]; }
        __syncthreads();
        const unsigned int b1 = sb1;
        const unsigned int above1 = sabove1;
        const bool fast = (scnt1 <= SELCAP);   // uniform across blocks (same data)
        if (fast) {
            // whole boundary bin fits in SELCAP: coarse threshold suffices
            tmin = b1 << 21;
        } else {
            // level-2 refinement over the boundary bin
            const int n = min(__ldcg(&g_ncand), NCAP);
            for (int i = gid; i < n; i += NB * NT) {
                const unsigned int hi = (unsigned int)(__ldcg(&g_cand[i]) >> 32);
                if ((hi >> 21) == b1) atomicAdd(&g_hist2[(hi >> 10) & 0x7FFu], 1u);
            }
            gbar();
            sm.scan.s[tid] = __ldcg(&g_hist2[tid]);
            sm.scan.s[tid + 1024] = __ldcg(&g_hist2[tid + 1024]);
            __syncthreads();
            suffix_scan_2048(sm.scan.s, tid);
            for (int b = tid; b < 2048; b += NT) {
                if (above1 + sm.scan.s[b] >= K &&
                    (b == 2047 || above1 + sm.scan.s[b + 1] < K)) {
                    stmin = (b1 << 21) | ((unsigned int)b << 10);
                }
            }
            if (tid == 0 && above1 + sm.scan.s[0] < K) stmin = (b1 << 21);
            __syncthreads();
            tmin = stmin;
        }
    }

    // ========== phase 3: compact survivors (uniform trip count) =================
    {
        const int n = min(__ldcg(&g_ncand), NCAP);
        const int stride = NB * NT;
        const int niter = (n + stride - 1) / stride;
        for (int t = 0; t < niter; t++) {
            const int i = gid + t * stride;
            unsigned long long key = 0ull;
            bool keep = false;
            if (i < n) {
                key = __ldcg(&g_cand[i]);
                keep = ((unsigned int)(key >> 32)) >= tmin;
            }
            const unsigned int mask = __ballot_sync(F, keep);
            if (mask) {
                const int leader = __ffs(mask) - 1;
                int base = 0;
                if (lane == leader) base = atomicAdd(&g_nsel, __popc(mask));
                base = __shfl_sync(F, base, leader);
                if (keep) {
                    const int off = __popc(mask & ((1u << lane) - 1u));
                    if (base + off < SELCAP) g_sel[base + off] = key;
                }
            }
        }
    }
    gbar();

    // ========== phase 4: rank (one warp/survivor) + emit + fused gather =========
    {
        const int nsel = min(__ldcg(&g_nsel), SELCAP);
        for (int i = tid; i < nsel; i += NT) sm.rank.keys[i] = __ldcg(&g_sel[i]);
        __syncthreads();
        const int gi = wid * NB + blockIdx.x;  // strided: spreads gather over blocks
        if (gi < nsel) {
            const unsigned long long key = sm.rank.keys[gi];
            unsigned int r = 0;
            for (int j = lane; j < nsel; j += 32)
                r += (sm.rank.keys[j] > key) ? 1u : 0u;
            r = __reduce_add_sync(F, r);   // exact rank, keys unique
            if (r < K) {
                const unsigned int hi = (unsigned int)(key >> 32);
                const unsigned int idx = 0xFFFFFFFFu - (unsigned int)key;
                if (lane == 0) {
                    out[OUT_KP + 2 * r + 0] = (float)(idx & (W - 1));
                    out[OUT_KP + 2 * r + 1] = (float)(idx >> 10);
                    out[OUT_SC + r] = __uint_as_float(hi & 0x7FFFFFFFu);
                    out[OUT_VALID + r] = 1.0f;
                }
                // fused descriptor gather + L2 normalize (4 channels per lane)
                float v0 = __ldg(&feat[(size_t)(lane)*(H * W) + idx]);
                float v1 = __ldg(&feat[(size_t)(lane + 32) * (H * W) + idx]);
                float v2 = __ldg(&feat[(size_t)(lane + 64) * (H * W) + idx]);
                float v3 = __ldg(&feat[(size_t)(lane + 96) * (H * W) + idx]);
                float ss = v0 * v0 + v1 * v1 + v2 * v2 + v3 * v3;
#pragma unroll
                for (int o = 16; o > 0; o >>= 1)
                    ss += __shfl_xor_sync(F, ss, o);
                const float inorm = 1.0f / fmaxf(sqrtf(ss), 1e-12f);
                float* drow = out + OUT_D + (size_t)r * D;
                drow[lane] = v0 * inorm;
                drow[lane + 32] = v1 * inorm;
                drow[lane + 64] = v2 * inorm;
                drow[lane + 96] = v3 * inorm;
            }
        } else if (gi < K) {  // padding rows when nsel < K (rows nsel..K-1)
            if (lane == 0) {
                out[OUT_KP + 2 * gi + 0] = 0.0f;
                out[OUT_KP + 2 * gi + 1] = 0.0f;
                out[OUT_SC + gi] = NEG_INF;
                out[OUT_VALID + gi] = 0.0f;
            }
            float* drow = out + OUT_D + (size_t)gi * D;
            drow[lane] = 0.0f;
            drow[lane + 32] = 0.0f;
            drow[lane + 64] = 0.0f;
            drow[lane + 96] = 0.0f;
        }
    }

    // ========== tail: last block to finish re-zeros ALL state for next replay ===
    __syncthreads();
    if (tid == 0) {
        __threadfence();
        slast = (atomicAdd(&g_done, 1u) == NB - 1) ? 1 : 0;
    }
    __syncthreads();
    if (slast) {
        unsigned int* h1 = &g_hist1[0][0];
        for (int i = tid; i < NH * 2048; i += NT) h1[i] = 0u;
        for (int i = tid; i < 2048; i += NT) g_hist2[i] = 0u;
        __syncthreads();
        if (tid == 0) { g_ncand = 0; g_nsel = 0; __threadfence(); g_done = 0u; }
    }
}

// ---------------- launch ---------------------------------------------------------
extern "C" void kernel_launch(void* const* d_in, const int* in_sizes, int n_in,
                              void* d_out, int out_size) {
    const float* feat = (const float*)d_in[0];
    const int* ow_p = (n_in > 1) ? (const int*)d_in[1] : nullptr;
    const int* oh_p = (n_in > 2) ? (const int*)d_in[2] : nullptr;
    float* out = (float*)d_out;
    disk_mega<<<NB, NT>>>(feat, ow_p, oh_p, out);
}

// round 11
// speedup vs baseline: 1.2608x; 1.1974x over previous
#include <cuda_runtime.h>
#include <cstdint>

#define H 1024
#define W 1024
#define D 128
#define K 2048
#define NCAP (1 << 20)
#define SELCAP 4096
#define NB 128            // blocks; <= 148 SMs so all co-resident
#define NT 1024
#define NH 8              // replicated hist1 copies
#define NEG_INF __int_as_float(0xFF800000)

// Output layout (float32): keypoints[K,2] | scores[K] | d[K,D] | valid[K]
#define OUT_KP 0
#define OUT_SC (K * 2)
#define OUT_D (K * 2 + K)
#define OUT_VALID (K * 2 + K + K * D)

// ---------------- scratch (static device globals; no allocation) ----------------
__device__ unsigned long long g_cand[NCAP];
__device__ unsigned long long g_sel[SELCAP];
__device__ int g_ncand;
__device__ int g_nsel;
__device__ unsigned int g_hist1[NH][2048];
__device__ unsigned int g_hist2[2048];
__device__ unsigned int g_barcnt;
__device__ volatile unsigned int g_bargen;
__device__ unsigned int g_done;

// ---------------- shared memory union (per-phase reuse) ----------------
struct __align__(16) DetSm {
    float tile[36][44];     // halo cols [bx-4, bx+36)
    float rowmax[36][33];
    unsigned long long list[1024];
    int cnt;
    int base;
};
struct ScanSm { unsigned int s[2048]; };
struct RankSm { unsigned long long keys[SELCAP]; };
union SmU { DetSm det; ScanSm scan; RankSm rank; };

// ---------------- software grid barrier (all NB blocks resident) ----------------
__device__ __forceinline__ void gbar() {
    __syncthreads();
    if (threadIdx.x == 0) {
        unsigned int gen = g_bargen;
        __threadfence();
        if (atomicAdd(&g_barcnt, 1u) == NB - 1) {
            g_barcnt = 0;
            __threadfence();
            g_bargen = gen + 1;
        } else {
            while (g_bargen == gen) { }
        }
        __threadfence();
    }
    __syncthreads();
}

__device__ __forceinline__ void suffix_scan_2048(unsigned int* s, int tid) {
    for (int off = 1; off < 2048; off <<= 1) {
        unsigned int a0 = (tid + off < 2048) ? s[tid + off] : 0u;
        unsigned int a1 = (tid + 1024 + off < 2048) ? s[tid + 1024 + off] : 0u;
        __syncthreads();
        s[tid] += a0;
        s[tid + 1024] += a1;
        __syncthreads();
    }
}

__global__ __launch_bounds__(NT, 1) void disk_mega(const float* __restrict__ feat,
                                                   const int* __restrict__ ow_p,
                                                   const int* __restrict__ oh_p,
                                                   float* __restrict__ out) {
    __shared__ SmU sm;
    __shared__ unsigned int sb1, sabove1, scnt1, stmin;
    __shared__ int slast;
    const unsigned int F = 0xFFFFFFFFu;
    const int tid = threadIdx.x;
    const int gid = blockIdx.x * NT + tid;
    const int lane = tid & 31;
    const int wid = tid >> 5;
    const float* heat = feat + (size_t)D * H * W;
    const int ow = ow_p ? __ldg(ow_p) : W;
    const int oh = oh_p ? __ldg(oh_p) : H;

    // ========== phase 1: tiled NMS detect (R7 emission + halo prefetch) =========
    {
        const int lx = lane, ly = wid;
        const int hc = blockIdx.x & (NH - 1);
        const int hr = tid / 10, hx = tid - hr * 10;   // halo loader coords (tid<360)
        int t = blockIdx.x;

        // prefetch tile 0 halo into registers
        float4 hv = make_float4(NEG_INF, NEG_INF, NEG_INF, NEG_INF);
        if (tid < 360) {
            const int bx = (t & 31) * 32, by = (t >> 5) * 32;
            const int gy = by - 2 + hr, gx0 = bx - 4 + hx * 4;
            if (gy >= 0 && gy < H && gx0 >= 0 && gx0 < W)
                hv = *(const float4*)(heat + (size_t)gy * W + gx0);
        }

        for (int it = 0; it < 8; it++) {
            const int bx = (t & 31) * 32, by = (t >> 5) * 32;
            if (tid < 360) *(float4*)&sm.det.tile[hr][hx * 4] = hv;
            if (tid == 0) sm.det.cnt = 0;
            __syncthreads();
            // kick off next tile's halo loads (overlaps with compute below)
            if (it < 7) {
                float4 nv = make_float4(NEG_INF, NEG_INF, NEG_INF, NEG_INF);
                if (tid < 360) {
                    const int tn = t + NB;
                    const int nbx = (tn & 31) * 32, nby = (tn >> 5) * 32;
                    const int gy = nby - 2 + hr, gx0 = nbx - 4 + hx * 4;
                    if (gy >= 0 && gy < H && gx0 >= 0 && gx0 < W)
                        nv = *(const float4*)(heat + (size_t)gy * W + gx0);
                }
                hv = nv;
            }
            // horizontal 5-max
            for (int i = tid; i < 36 * 32; i += NT) {
                const int ty = i >> 5, tx = i & 31;
                const float* row = sm.det.tile[ty];
                sm.det.rowmax[ty][tx] =
                    fmaxf(fmaxf(fmaxf(row[tx + 2], row[tx + 3]),
                                fmaxf(row[tx + 4], row[tx + 5])),
                          row[tx + 6]);
            }
            __syncthreads();
            // vertical 5-max + candidate test -> smem list (cheap ATOMS)
            const float v = sm.det.tile[ly + 2][lx + 4];
            const float m =
                fmaxf(fmaxf(fmaxf(sm.det.rowmax[ly][lx], sm.det.rowmax[ly + 1][lx]),
                            fmaxf(sm.det.rowmax[ly + 2][lx], sm.det.rowmax[ly + 3][lx])),
                      sm.det.rowmax[ly + 4][lx]);
            const int x = bx + lx, y = by + ly;
            if (v > 0.0f && v == m && x <= ow - 1 && y <= oh - 1) {
                const unsigned int uk = __float_as_uint(v) | 0x80000000u;
                const unsigned int idx = (unsigned int)(y * W + x);
                const int p = atomicAdd(&sm.det.cnt, 1);
                sm.det.list[p] = ((unsigned long long)uk << 32) | (0xFFFFFFFFu - idx);
                atomicAdd(&g_hist1[hc][uk >> 21], 1u);
            }
            __syncthreads();
            if (tid == 0) sm.det.base = atomicAdd(&g_ncand, sm.det.cnt);
            __syncthreads();
            const int cnt = sm.det.cnt, base = sm.det.base;
            for (int i = tid; i < cnt; i += NT) g_cand[base + i] = sm.det.list[i];
            __syncthreads();
            t += NB;
        }
    }
    gbar();

    // ========== phase 2: scan1 -> b1; fast-path threshold or level-2 refine =====
    unsigned int tmin;
    {
        unsigned int a0 = 0u, a1 = 0u;
#pragma unroll
        for (int c = 0; c < NH; c++) {
            a0 += __ldcg(&g_hist1[c][tid]);
            a1 += __ldcg(&g_hist1[c][tid + 1024]);
        }
        sm.scan.s[tid] = a0;
        sm.scan.s[tid + 1024] = a1;
        __syncthreads();
        suffix_scan_2048(sm.scan.s, tid);
        for (int b = tid; b < 2048; b += NT) {
            if (sm.scan.s[b] >= K && (b == 2047 || sm.scan.s[b + 1] < K)) {
                sb1 = (unsigned int)b;
                sabove1 = (b < 2047) ? sm.scan.s[b + 1] : 0u;
                scnt1 = sm.scan.s[b];
            }
        }
        if (tid == 0 && sm.scan.s[0] < K) { sb1 = 0u; sabove1 = 0u; scnt1 = sm.scan.s[0]; }
        __syncthreads();
        const unsigned int b1 = sb1;
        const unsigned int above1 = sabove1;
        const bool fast = (scnt1 <= SELCAP);   // uniform across blocks (same data)
        if (fast) {
            tmin = b1 << 21;   // whole boundary bin fits in SELCAP
        } else {
            const int n = min(__ldcg(&g_ncand), NCAP);
            for (int i = gid; i < n; i += NB * NT) {
                const unsigned int hi = (unsigned int)(__ldcg(&g_cand[i]) >> 32);
                if ((hi >> 21) == b1) atomicAdd(&g_hist2[(hi >> 10) & 0x7FFu], 1u);
            }
            gbar();
            sm.scan.s[tid] = __ldcg(&g_hist2[tid]);
            sm.scan.s[tid + 1024] = __ldcg(&g_hist2[tid + 1024]);
            __syncthreads();
            suffix_scan_2048(sm.scan.s, tid);
            for (int b = tid; b < 2048; b += NT) {
                if (above1 + sm.scan.s[b] >= K &&
                    (b == 2047 || above1 + sm.scan.s[b + 1] < K)) {
                    stmin = (b1 << 21) | ((unsigned int)b << 10);
                }
            }
            if (tid == 0 && above1 + sm.scan.s[0] < K) stmin = (b1 << 21);
            __syncthreads();
            tmin = stmin;
        }
    }

    // ========== phase 3: compact survivors (uniform trip count) =================
    {
        const int n = min(__ldcg(&g_ncand), NCAP);
        const int stride = NB * NT;
        const int niter = (n + stride - 1) / stride;
        for (int t = 0; t < niter; t++) {
            const int i = gid + t * stride;
            unsigned long long key = 0ull;
            bool keep = false;
            if (i < n) {
                key = __ldcg(&g_cand[i]);
                keep = ((unsigned int)(key >> 32)) >= tmin;
            }
            const unsigned int mask = __ballot_sync(F, keep);
            if (mask) {
                const int leader = __ffs(mask) - 1;
                int base = 0;
                if (lane == leader) base = atomicAdd(&g_nsel, __popc(mask));
                base = __shfl_sync(F, base, leader);
                if (keep) {
                    const int off = __popc(mask & ((1u << lane) - 1u));
                    if (base + off < SELCAP) g_sel[base + off] = key;
                }
            }
        }
    }
    gbar();

    // ========== phase 4: rank (one warp/survivor) + emit + fused gather =========
    {
        const int nsel = min(__ldcg(&g_nsel), SELCAP);
        for (int i = tid; i < nsel; i += NT) sm.rank.keys[i] = __ldcg(&g_sel[i]);
        __syncthreads();
        const int gi = wid * NB + blockIdx.x;  // strided: spreads gather over blocks
        if (gi < nsel) {
            const unsigned long long key = sm.rank.keys[gi];
            unsigned int r = 0;
            for (int j = lane; j < nsel; j += 32)
                r += (sm.rank.keys[j] > key) ? 1u : 0u;
            r = __reduce_add_sync(F, r);   // exact rank, keys unique
            if (r < K) {
                const unsigned int hi = (unsigned int)(key >> 32);
                const unsigned int idx = 0xFFFFFFFFu - (unsigned int)key;
                if (lane == 0) {
                    out[OUT_KP + 2 * r + 0] = (float)(idx & (W - 1));
                    out[OUT_KP + 2 * r + 1] = (float)(idx >> 10);
                    out[OUT_SC + r] = __uint_as_float(hi & 0x7FFFFFFFu);
                    out[OUT_VALID + r] = 1.0f;
                }
                // fused descriptor gather + L2 normalize (4 channels per lane)
                float v0 = __ldg(&feat[(size_t)(lane)*(H * W) + idx]);
                float v1 = __ldg(&feat[(size_t)(lane + 32) * (H * W) + idx]);
                float v2 = __ldg(&feat[(size_t)(lane + 64) * (H * W) + idx]);
                float v3 = __ldg(&feat[(size_t)(lane + 96) * (H * W) + idx]);
                float ss = v0 * v0 + v1 * v1 + v2 * v2 + v3 * v3;
#pragma unroll
                for (int o = 16; o > 0; o >>= 1)
                    ss += __shfl_xor_sync(F, ss, o);
                const float inorm = 1.0f / fmaxf(sqrtf(ss), 1e-12f);
                float* drow = out + OUT_D + (size_t)r * D;
                drow[lane] = v0 * inorm;
                drow[lane + 32] = v1 * inorm;
                drow[lane + 64] = v2 * inorm;
                drow[lane + 96] = v3 * inorm;
            }
        } else if (gi < K) {  // padding rows when nsel < K (rows nsel..K-1)
            if (lane == 0) {
                out[OUT_KP + 2 * gi + 0] = 0.0f;
                out[OUT_KP + 2 * gi + 1] = 0.0f;
                out[OUT_SC + gi] = NEG_INF;
                out[OUT_VALID + gi] = 0.0f;
            }
            float* drow = out + OUT_D + (size_t)gi * D;
            drow[lane] = 0.0f;
            drow[lane + 32] = 0.0f;
            drow[lane + 64] = 0.0f;
            drow[lane + 96] = 0.0f;
        }
    }

    // ========== tail: last block to finish re-zeros ALL state for next replay ===
    __syncthreads();
    if (tid == 0) {
        __threadfence();
        slast = (atomicAdd(&g_done, 1u) == NB - 1) ? 1 : 0;
    }
    __syncthreads();
    if (slast) {
        unsigned int* h1 = &g_hist1[0][0];
        for (int i = tid; i < NH * 2048; i += NT) h1[i] = 0u;
        for (int i = tid; i < 2048; i += NT) g_hist2[i] = 0u;
        __syncthreads();
        if (tid == 0) { g_ncand = 0; g_nsel = 0; __threadfence(); g_done = 0u; }
    }
}

// ---------------- launch ---------------------------------------------------------
extern "C" void kernel_launch(void* const* d_in, const int* in_sizes, int n_in,
                              void* d_out, int out_size) {
    const float* feat = (const float*)d_in[0];
    const int* ow_p = (n_in > 1) ? (const int*)d_in[1] : nullptr;
    const int* oh_p = (n_in > 2) ? (const int*)d_in[2] : nullptr;
    float* out = (float*)d_out;
    disk_mega<<<NB, NT>>>(feat, ow_p, oh_p, out);
}

// round 12
// speedup vs baseline: 1.4923x; 1.1837x over previous
#include <cuda_runtime.h>
#include <cstdint>

#define H 1024
#define W 1024
#define D 128
#define K 2048
#define NCAP (1 << 20)
#define SELCAP 4096
#define NB 128            // blocks; <= SM count so all co-resident
#define NT 1024
#define NH 8              // replicated hist1 copies
#define NEG_INF __int_as_float(0xFF800000)

// detect tiling: 64x64 output tiles, 16x16 = 256 tiles, 2 per block
#define TS 64
#define HALO_ROWS 68      // TS + 4
#define HALO_F4 18        // (TS + 8) / 4 float4 per row
#define HALO_TASKS (HALO_ROWS * HALO_F4)   // 1224

// Output layout (float32): keypoints[K,2] | scores[K] | d[K,D] | valid[K]
#define OUT_KP 0
#define OUT_SC (K * 2)
#define OUT_D (K * 2 + K)
#define OUT_VALID (K * 2 + K + K * D)

// ---------------- scratch (static device globals; no allocation) ----------------
__device__ unsigned long long g_cand[NCAP];
__device__ unsigned long long g_sel[SELCAP];
__device__ int g_ncand;
__device__ int g_nsel;
__device__ unsigned int g_hist1[NH][2048];
__device__ unsigned int g_hist2[2048];
__device__ unsigned int g_barcnt;
__device__ volatile unsigned int g_bargen;
__device__ unsigned int g_done;

// ---------------- shared memory union (per-phase reuse) ----------------
struct __align__(16) DetSm {
    float tile[HALO_ROWS][76];     // cols bx-4 .. bx+67 (72 used, padded to 76)
    float rowmax[HALO_ROWS][68];   // hmax output, cols 0..63 used
    unsigned long long list[1024];
    int cnt;
    int base;
};
struct ScanSm { unsigned int s[2048]; };
struct RankSm { unsigned long long keys[SELCAP]; };
union SmU { DetSm det; ScanSm scan; RankSm rank; };

// ---------------- software grid barrier (all NB blocks resident) ----------------
__device__ __forceinline__ void gbar() {
    __syncthreads();
    if (threadIdx.x == 0) {
        unsigned int gen = g_bargen;
        __threadfence();
        if (atomicAdd(&g_barcnt, 1u) == NB - 1) {
            g_barcnt = 0;
            __threadfence();
            g_bargen = gen + 1;
        } else {
            while (g_bargen == gen) { }
        }
        __threadfence();
    }
    __syncthreads();
}

__device__ __forceinline__ void suffix_scan_2048(unsigned int* s, int tid) {
    for (int off = 1; off < 2048; off <<= 1) {
        unsigned int a0 = (tid + off < 2048) ? s[tid + off] : 0u;
        unsigned int a1 = (tid + 1024 + off < 2048) ? s[tid + 1024 + off] : 0u;
        __syncthreads();
        s[tid] += a0;
        s[tid + 1024] += a1;
        __syncthreads();
    }
}

// halo loader: tile t, task i (0..HALO_TASKS-1) -> float4
__device__ __forceinline__ float4 halo_ld(const float* __restrict__ heat, int t, int i) {
    const int bx = (t & 15) * TS, by = (t >> 4) * TS;
    const int r = i / HALO_F4, c = i - r * HALO_F4;
    const int gy = by - 2 + r;
    const int gx0 = bx - 4 + c * 4;
    if (gy >= 0 && gy < H && gx0 >= 0 && gx0 <= W - 4)
        return *(const float4*)(heat + (size_t)gy * W + gx0);
    return make_float4(NEG_INF, NEG_INF, NEG_INF, NEG_INF);
}

__global__ __launch_bounds__(NT, 1) void disk_mega(const float* __restrict__ feat,
                                                   const int* __restrict__ ow_p,
                                                   const int* __restrict__ oh_p,
                                                   float* __restrict__ out) {
    __shared__ SmU sm;
    __shared__ unsigned int sb1, sabove1, scnt1, stmin;
    __shared__ int slast;
    const unsigned int F = 0xFFFFFFFFu;
    const int tid = threadIdx.x;
    const int gid = blockIdx.x * NT + tid;
    const int lane = tid & 31;
    const int wid = tid >> 5;
    const float* heat = feat + (size_t)D * H * W;
    const int ow = ow_p ? __ldg(ow_p) : W;
    const int oh = oh_p ? __ldg(oh_p) : H;

    // ========== phase 1: NMS detect, 64x64 tiles, 2 per block ===================
    {
        const int hc = blockIdx.x & (NH - 1);
        const int i0 = tid, i1 = tid + NT;   // halo tasks (i1 may be inactive)
        int t = blockIdx.x;

        // prefetch tile 0 halo
        float4 h0 = halo_ld(heat, t, i0);
        float4 h1 = (i1 < HALO_TASKS) ? halo_ld(heat, t, i1)
                                      : make_float4(0.f, 0.f, 0.f, 0.f);

        for (int it = 0; it < 2; it++) {
            const int bx = (t & 15) * TS, by = (t >> 4) * TS;
            {   // store halo to smem
                const int r0 = i0 / HALO_F4, c0 = i0 - r0 * HALO_F4;
                *(float4*)&sm.det.tile[r0][c0 * 4] = h0;
                if (i1 < HALO_TASKS) {
                    const int r1 = i1 / HALO_F4, c1 = i1 - r1 * HALO_F4;
                    *(float4*)&sm.det.tile[r1][c1 * 4] = h1;
                }
            }
            if (tid == 0) sm.det.cnt = 0;
            __syncthreads();
            // prefetch next tile's halo (overlaps with compute below)
            if (it == 0) {
                h0 = halo_ld(heat, t + NB, i0);
                if (i1 < HALO_TASKS) h1 = halo_ld(heat, t + NB, i1);
            }
            // horizontal 5-max: 68 rows x 64 output cols
#pragma unroll
            for (int k = 0; k < 5; k++) {          // ceil(68*64/1024)=4.25 -> 5 w/ guard
                const int i = tid + k * NT;
                if (i < HALO_ROWS * TS) {
                    const int ty = i >> 6, tx = i & 63;
                    const float* row = sm.det.tile[ty];
                    sm.det.rowmax[ty][tx] =
                        fmaxf(fmaxf(fmaxf(row[tx + 2], row[tx + 3]),
                                    fmaxf(row[tx + 4], row[tx + 5])),
                              row[tx + 6]);
                }
            }
            __syncthreads();
            // vertical 5-max + candidate test -> smem list (4 outputs per thread)
#pragma unroll
            for (int k = 0; k < 4; k++) {
                const int i = tid + k * NT;
                const int oy = i >> 6, ox = i & 63;
                const float v = sm.det.tile[oy + 2][ox + 4];
                const float m =
                    fmaxf(fmaxf(fmaxf(sm.det.rowmax[oy][ox], sm.det.rowmax[oy + 1][ox]),
                                fmaxf(sm.det.rowmax[oy + 2][ox], sm.det.rowmax[oy + 3][ox])),
                          sm.det.rowmax[oy + 4][ox]);
                const int x = bx + ox, y = by + oy;
                if (v > 0.0f && v == m && x <= ow - 1 && y <= oh - 1) {
                    const unsigned int uk = __float_as_uint(v) | 0x80000000u;
                    const unsigned int idx = (unsigned int)(y * W + x);
                    const int p = atomicAdd(&sm.det.cnt, 1);
                    sm.det.list[p] = ((unsigned long long)uk << 32) | (0xFFFFFFFFu - idx);
                    atomicAdd(&g_hist1[hc][uk >> 21], 1u);
                }
            }
            __syncthreads();
            if (tid == 0) sm.det.base = atomicAdd(&g_ncand, sm.det.cnt);
            __syncthreads();
            const int cnt = sm.det.cnt, base = sm.det.base;
            for (int i = tid; i < cnt; i += NT) g_cand[base + i] = sm.det.list[i];
            __syncthreads();
            t += NB;
        }
    }
    gbar();

    // ========== phase 2: scan1 -> b1; fast-path threshold or level-2 refine =====
    unsigned int tmin;
    {
        unsigned int a0 = 0u, a1 = 0u;
#pragma unroll
        for (int c = 0; c < NH; c++) {
            a0 += __ldcg(&g_hist1[c][tid]);
            a1 += __ldcg(&g_hist1[c][tid + 1024]);
        }
        sm.scan.s[tid] = a0;
        sm.scan.s[tid + 1024] = a1;
        __syncthreads();
        suffix_scan_2048(sm.scan.s, tid);
        for (int b = tid; b < 2048; b += NT) {
            if (sm.scan.s[b] >= K && (b == 2047 || sm.scan.s[b + 1] < K)) {
                sb1 = (unsigned int)b;
                sabove1 = (b < 2047) ? sm.scan.s[b + 1] : 0u;
                scnt1 = sm.scan.s[b];
            }
        }
        if (tid == 0 && sm.scan.s[0] < K) { sb1 = 0u; sabove1 = 0u; scnt1 = sm.scan.s[0]; }
        __syncthreads();
        const unsigned int b1 = sb1;
        const unsigned int above1 = sabove1;
        const bool fast = (scnt1 <= SELCAP);   // uniform across blocks (same data)
        if (fast) {
            tmin = b1 << 21;   // whole boundary bin fits in SELCAP
        } else {
            const int n = min(__ldcg(&g_ncand), NCAP);
            for (int i = gid; i < n; i += NB * NT) {
                const unsigned int hi = (unsigned int)(__ldcg(&g_cand[i]) >> 32);
                if ((hi >> 21) == b1) atomicAdd(&g_hist2[(hi >> 10) & 0x7FFu], 1u);
            }
            gbar();
            sm.scan.s[tid] = __ldcg(&g_hist2[tid]);
            sm.scan.s[tid + 1024] = __ldcg(&g_hist2[tid + 1024]);
            __syncthreads();
            suffix_scan_2048(sm.scan.s, tid);
            for (int b = tid; b < 2048; b += NT) {
                if (above1 + sm.scan.s[b] >= K &&
                    (b == 2047 || above1 + sm.scan.s[b + 1] < K)) {
                    stmin = (b1 << 21) | ((unsigned int)b << 10);
                }
            }
            if (tid == 0 && above1 + sm.scan.s[0] < K) stmin = (b1 << 21);
            __syncthreads();
            tmin = stmin;
        }
    }

    // ========== phase 3: compact survivors (uniform trip count) =================
    {
        const int n = min(__ldcg(&g_ncand), NCAP);
        const int stride = NB * NT;
        const int niter = (n + stride - 1) / stride;
        for (int t = 0; t < niter; t++) {
            const int i = gid + t * stride;
            unsigned long long key = 0ull;
            bool keep = false;
            if (i < n) {
                key = __ldcg(&g_cand[i]);
                keep = ((unsigned int)(key >> 32)) >= tmin;
            }
            const unsigned int mask = __ballot_sync(F, keep);
            if (mask) {
                const int leader = __ffs(mask) - 1;
                int base = 0;
                if (lane == leader) base = atomicAdd(&g_nsel, __popc(mask));
                base = __shfl_sync(F, base, leader);
                if (keep) {
                    const int off = __popc(mask & ((1u << lane) - 1u));
                    if (base + off < SELCAP) g_sel[base + off] = key;
                }
            }
        }
    }
    gbar();

    // ========== phase 4: rank (one warp/survivor) + emit + fused gather =========
    {
        const int nsel = min(__ldcg(&g_nsel), SELCAP);
        for (int i = tid; i < nsel; i += NT) sm.rank.keys[i] = __ldcg(&g_sel[i]);
        __syncthreads();
        const int gi = wid * NB + blockIdx.x;  // strided: spreads gather over blocks
        if (gi < nsel) {
            const unsigned long long key = sm.rank.keys[gi];
            unsigned int r = 0;
            for (int j = lane; j < nsel; j += 32)
                r += (sm.rank.keys[j] > key) ? 1u : 0u;
            r = __reduce_add_sync(F, r);   // exact rank, keys unique
            if (r < K) {
                const unsigned int hi = (unsigned int)(key >> 32);
                const unsigned int idx = 0xFFFFFFFFu - (unsigned int)key;
                if (lane == 0) {
                    out[OUT_KP + 2 * r + 0] = (float)(idx & (W - 1));
                    out[OUT_KP + 2 * r + 1] = (float)(idx >> 10);
                    out[OUT_SC + r] = __uint_as_float(hi & 0x7FFFFFFFu);
                    out[OUT_VALID + r] = 1.0f;
                }
                // fused descriptor gather + L2 normalize (4 channels per lane)
                float v0 = __ldg(&feat[(size_t)(lane)*(H * W) + idx]);
                float v1 = __ldg(&feat[(size_t)(lane + 32) * (H * W) + idx]);
                float v2 = __ldg(&feat[(size_t)(lane + 64) * (H * W) + idx]);
                float v3 = __ldg(&feat[(size_t)(lane + 96) * (H * W) + idx]);
                float ss = v0 * v0 + v1 * v1 + v2 * v2 + v3 * v3;
#pragma unroll
                for (int o = 16; o > 0; o >>= 1)
                    ss += __shfl_xor_sync(F, ss, o);
                const float inorm = 1.0f / fmaxf(sqrtf(ss), 1e-12f);
                float* drow = out + OUT_D + (size_t)r * D;
                drow[lane] = v0 * inorm;
                drow[lane + 32] = v1 * inorm;
                drow[lane + 64] = v2 * inorm;
                drow[lane + 96] = v3 * inorm;
            }
        } else if (gi < K) {  // padding rows when nsel < K (rows nsel..K-1)
            if (lane == 0) {
                out[OUT_KP + 2 * gi + 0] = 0.0f;
                out[OUT_KP + 2 * gi + 1] = 0.0f;
                out[OUT_SC + gi] = NEG_INF;
                out[OUT_VALID + gi] = 0.0f;
            }
            float* drow = out + OUT_D + (size_t)gi * D;
            drow[lane] = 0.0f;
            drow[lane + 32] = 0.0f;
            drow[lane + 64] = 0.0f;
            drow[lane + 96] = 0.0f;
        }
    }

    // ========== tail: last block to finish re-zeros ALL state for next replay ===
    __syncthreads();
    if (tid == 0) {
        __threadfence();
        slast = (atomicAdd(&g_done, 1u) == NB - 1) ? 1 : 0;
    }
    __syncthreads();
    if (slast) {
        unsigned int* h1 = &g_hist1[0][0];
        for (int i = tid; i < NH * 2048; i += NT) h1[i] = 0u;
        for (int i = tid; i < 2048; i += NT) g_hist2[i] = 0u;
        __syncthreads();
        if (tid == 0) { g_ncand = 0; g_nsel = 0; __threadfence(); g_done = 0u; }
    }
}

// ---------------- launch ---------------------------------------------------------
extern "C" void kernel_launch(void* const* d_in, const int* in_sizes, int n_in,
                              void* d_out, int out_size) {
    const float* feat = (const float*)d_in[0];
    const int* ow_p = (n_in > 1) ? (const int*)d_in[1] : nullptr;
    const int* oh_p = (n_in > 2) ? (const int*)d_in[2] : nullptr;
    float* out = (float*)d_out;
    disk_mega<<<NB, NT>>>(feat, ow_p, oh_p, out);
}

// round 13
// speedup vs baseline: 1.5156x; 1.0156x over previous
#include <cuda_runtime.h>
#include <cstdint>

#define H 1024
#define W 1024
#define D 128
#define K 2048
#define NCAP (1 << 20)
#define SELCAP 4096
#define NB 128            // blocks == number of detect tiles; all co-resident
#define NT 1024
#define NH 8              // replicated hist1 copies
#define NEG_INF __int_as_float(0xFF800000)

// detect tiling: 128(w) x 64(h) output tiles, 8 x 16 = 128 tiles, ONE per block
#define TSX 128
#define TSY 64
#define HALO_ROWS (TSY + 4)        // 68
#define HALO_F4 ((TSX + 8) / 4)    // 34 float4 per row
#define HALO_TASKS (HALO_ROWS * HALO_F4)   // 2312
#define TILE_PITCH 140             // 136 used + pad
#define RM_PITCH 132               // 128 used + pad

// Output layout (float32): keypoints[K,2] | scores[K] | d[K,D] | valid[K]
#define OUT_KP 0
#define OUT_SC (K * 2)
#define OUT_D (K * 2 + K)
#define OUT_VALID (K * 2 + K + K * D)

// ---------------- scratch (static device globals; no allocation) ----------------
__device__ unsigned long long g_cand[NCAP];
__device__ unsigned long long g_sel[SELCAP];
__device__ int g_ncand;
__device__ int g_nsel;
__device__ unsigned int g_hist1[NH][2048];
__device__ unsigned int g_hist2[2048];
__device__ unsigned int g_barcnt;
__device__ volatile unsigned int g_bargen;
__device__ unsigned int g_done;

// ---------------- dynamic shared memory union (per-phase reuse) -----------------
struct __align__(16) DetSm {
    float tile[HALO_ROWS][TILE_PITCH];   // cols bx-4 .. bx+131
    float rowmax[HALO_ROWS][RM_PITCH];   // hmax output, cols 0..127 used
    unsigned long long list[1024];
    int cnt;
    int base;
};
struct ScanSm { unsigned int s[2048]; };
struct RankSm { unsigned long long keys[SELCAP]; };
union SmU { DetSm det; ScanSm scan; RankSm rank; };

// ---------------- software grid barrier (all NB blocks resident) ----------------
__device__ __forceinline__ void gbar() {
    __syncthreads();
    if (threadIdx.x == 0) {
        unsigned int gen = g_bargen;
        __threadfence();
        if (atomicAdd(&g_barcnt, 1u) == NB - 1) {
            g_barcnt = 0;
            __threadfence();
            g_bargen = gen + 1;
        } else {
            while (g_bargen == gen) { }
        }
        __threadfence();
    }
    __syncthreads();
}

__device__ __forceinline__ void suffix_scan_2048(unsigned int* s, int tid) {
    for (int off = 1; off < 2048; off <<= 1) {
        unsigned int a0 = (tid + off < 2048) ? s[tid + off] : 0u;
        unsigned int a1 = (tid + 1024 + off < 2048) ? s[tid + 1024 + off] : 0u;
        __syncthreads();
        s[tid] += a0;
        s[tid + 1024] += a1;
        __syncthreads();
    }
}

__global__ __launch_bounds__(NT, 1) void disk_mega(const float* __restrict__ feat,
                                                   const int* __restrict__ ow_p,
                                                   const int* __restrict__ oh_p,
                                                   float* __restrict__ out) {
    extern __shared__ char smem_raw[];
    SmU& sm = *reinterpret_cast<SmU*>(smem_raw);
    __shared__ unsigned int sb1, sabove1, scnt1, stmin;
    __shared__ int slast;
    const unsigned int F = 0xFFFFFFFFu;
    const int tid = threadIdx.x;
    const int gid = blockIdx.x * NT + tid;
    const int lane = tid & 31;
    const int wid = tid >> 5;
    const float* heat = feat + (size_t)D * H * W;
    const int ow = ow_p ? __ldg(ow_p) : W;
    const int oh = oh_p ? __ldg(oh_p) : H;

    // ========== phase 1: NMS detect, ONE 128x64 tile per block ==================
    {
        const int t = blockIdx.x;
        const int bx = (t & 7) * TSX, by = (t >> 3) * TSY;
        const int hc = blockIdx.x & (NH - 1);

        // halo load: all tasks issued in one batch (MLP ~2.3/thread)
#pragma unroll
        for (int k = 0; k < 3; k++) {
            const int i = tid + k * NT;
            if (i < HALO_TASKS) {
                const int r = i / HALO_F4, c = i - r * HALO_F4;
                const int gy = by - 2 + r;
                const int gx0 = bx - 4 + c * 4;
                float4 v;
                if (gy >= 0 && gy < H && gx0 >= 0 && gx0 <= W - 4)
                    v = *(const float4*)(heat + (size_t)gy * W + gx0);
                else
                    v = make_float4(NEG_INF, NEG_INF, NEG_INF, NEG_INF);
                *(float4*)&sm.det.tile[r][c * 4] = v;
            }
        }
        if (tid == 0) sm.det.cnt = 0;
        __syncthreads();
        // horizontal 5-max: 68 rows x 128 output cols (center = tile col tx+4)
#pragma unroll
        for (int k = 0; k < 9; k++) {
            const int i = tid + k * NT;
            if (i < HALO_ROWS * TSX) {
                const int ty = i >> 7, tx = i & 127;
                const float* row = sm.det.tile[ty];
                sm.det.rowmax[ty][tx] =
                    fmaxf(fmaxf(fmaxf(row[tx + 2], row[tx + 3]),
                                fmaxf(row[tx + 4], row[tx + 5])),
                          row[tx + 6]);
            }
        }
        __syncthreads();
        // vertical 5-max + candidate test -> smem list (8 outputs per thread)
#pragma unroll
        for (int k = 0; k < 8; k++) {
            const int i = tid + k * NT;
            const int oy = i >> 7, ox = i & 127;
            const float v = sm.det.tile[oy + 2][ox + 4];
            const float m =
                fmaxf(fmaxf(fmaxf(sm.det.rowmax[oy][ox], sm.det.rowmax[oy + 1][ox]),
                            fmaxf(sm.det.rowmax[oy + 2][ox], sm.det.rowmax[oy + 3][ox])),
                      sm.det.rowmax[oy + 4][ox]);
            const int x = bx + ox, y = by + oy;
            if (v > 0.0f && v == m && x <= ow - 1 && y <= oh - 1) {
                const unsigned int uk = __float_as_uint(v) | 0x80000000u;
                const unsigned int idx = (unsigned int)(y * W + x);
                const int p = atomicAdd(&sm.det.cnt, 1);
                sm.det.list[p] = ((unsigned long long)uk << 32) | (0xFFFFFFFFu - idx);
                atomicAdd(&g_hist1[hc][uk >> 21], 1u);
            }
        }
        __syncthreads();
        if (tid == 0) sm.det.base = atomicAdd(&g_ncand, sm.det.cnt);
        __syncthreads();
        const int cnt = sm.det.cnt, base = sm.det.base;
        for (int i = tid; i < cnt; i += NT) g_cand[base + i] = sm.det.list[i];
    }
    gbar();

    // ========== phase 2: scan1 -> b1; fast-path threshold or level-2 refine =====
    unsigned int tmin;
    {
        unsigned int a0 = 0u, a1 = 0u;
#pragma unroll
        for (int c = 0; c < NH; c++) {
            a0 += __ldcg(&g_hist1[c][tid]);
            a1 += __ldcg(&g_hist1[c][tid + 1024]);
        }
        sm.scan.s[tid] = a0;
        sm.scan.s[tid + 1024] = a1;
        __syncthreads();
        suffix_scan_2048(sm.scan.s, tid);
        for (int b = tid; b < 2048; b += NT) {
            if (sm.scan.s[b] >= K && (b == 2047 || sm.scan.s[b + 1] < K)) {
                sb1 = (unsigned int)b;
                sabove1 = (b < 2047) ? sm.scan.s[b + 1] : 0u;
                scnt1 = sm.scan.s[b];
            }
        }
        if (tid == 0 && sm.scan.s[0] < K) { sb1 = 0u; sabove1 = 0u; scnt1 = sm.scan.s[0]; }
        __syncthreads();
        const unsigned int b1 = sb1;
        const unsigned int above1 = sabove1;
        const bool fast = (scnt1 <= SELCAP);   // uniform across blocks (same data)
        if (fast) {
            tmin = b1 << 21;   // whole boundary bin fits in SELCAP
        } else {
            const int n = min(__ldcg(&g_ncand), NCAP);
            for (int i = gid; i < n; i += NB * NT) {
                const unsigned int hi = (unsigned int)(__ldcg(&g_cand[i]) >> 32);
                if ((hi >> 21) == b1) atomicAdd(&g_hist2[(hi >> 10) & 0x7FFu], 1u);
            }
            gbar();
            sm.scan.s[tid] = __ldcg(&g_hist2[tid]);
            sm.scan.s[tid + 1024] = __ldcg(&g_hist2[tid + 1024]);
            __syncthreads();
            suffix_scan_2048(sm.scan.s, tid);
            for (int b = tid; b < 2048; b += NT) {
                if (above1 + sm.scan.s[b] >= K &&
                    (b == 2047 || above1 + sm.scan.s[b + 1] < K)) {
                    stmin = (b1 << 21) | ((unsigned int)b << 10);
                }
            }
            if (tid == 0 && above1 + sm.scan.s[0] < K) stmin = (b1 << 21);
            __syncthreads();
            tmin = stmin;
        }
    }

    // ========== phase 3: compact survivors (uniform trip count) =================
    {
        const int n = min(__ldcg(&g_ncand), NCAP);
        const int stride = NB * NT;
        const int niter = (n + stride - 1) / stride;
        for (int t = 0; t < niter; t++) {
            const int i = gid + t * stride;
            unsigned long long key = 0ull;
            bool keep = false;
            if (i < n) {
                key = __ldcg(&g_cand[i]);
                keep = ((unsigned int)(key >> 32)) >= tmin;
            }
            const unsigned int mask = __ballot_sync(F, keep);
            if (mask) {
                const int leader = __ffs(mask) - 1;
                int base = 0;
                if (lane == leader) base = atomicAdd(&g_nsel, __popc(mask));
                base = __shfl_sync(F, base, leader);
                if (keep) {
                    const int off = __popc(mask & ((1u << lane) - 1u));
                    if (base + off < SELCAP) g_sel[base + off] = key;
                }
            }
        }
    }
    gbar();

    // ========== phase 4: rank (one warp/survivor) + emit + fused gather =========
    {
        const int nsel = min(__ldcg(&g_nsel), SELCAP);
        for (int i = tid; i < nsel; i += NT) sm.rank.keys[i] = __ldcg(&g_sel[i]);
        __syncthreads();
        const int gi = wid * NB + blockIdx.x;  // strided: spreads gather over blocks
        if (gi < nsel) {
            const unsigned long long key = sm.rank.keys[gi];
            unsigned int r = 0;
            for (int j = lane; j < nsel; j += 32)
                r += (sm.rank.keys[j] > key) ? 1u : 0u;
            r = __reduce_add_sync(F, r);   // exact rank, keys unique
            if (r < K) {
                const unsigned int hi = (unsigned int)(key >> 32);
                const unsigned int idx = 0xFFFFFFFFu - (unsigned int)key;
                if (lane == 0) {
                    out[OUT_KP + 2 * r + 0] = (float)(idx & (W - 1));
                    out[OUT_KP + 2 * r + 1] = (float)(idx >> 10);
                    out[OUT_SC + r] = __uint_as_float(hi & 0x7FFFFFFFu);
                    out[OUT_VALID + r] = 1.0f;
                }
                // fused descriptor gather + L2 normalize (4 channels per lane)
                float v0 = __ldg(&feat[(size_t)(lane)*(H * W) + idx]);
                float v1 = __ldg(&feat[(size_t)(lane + 32) * (H * W) + idx]);
                float v2 = __ldg(&feat[(size_t)(lane + 64) * (H * W) + idx]);
                float v3 = __ldg(&feat[(size_t)(lane + 96) * (H * W) + idx]);
                float ss = v0 * v0 + v1 * v1 + v2 * v2 + v3 * v3;
#pragma unroll
                for (int o = 16; o > 0; o >>= 1)
                    ss += __shfl_xor_sync(F, ss, o);
                const float inorm = 1.0f / fmaxf(sqrtf(ss), 1e-12f);
                float* drow = out + OUT_D + (size_t)r * D;
                drow[lane] = v0 * inorm;
                drow[lane + 32] = v1 * inorm;
                drow[lane + 64] = v2 * inorm;
                drow[lane + 96] = v3 * inorm;
            }
        } else if (gi < K) {  // padding rows when nsel < K (rows nsel..K-1)
            if (lane == 0) {
                out[OUT_KP + 2 * gi + 0] = 0.0f;
                out[OUT_KP + 2 * gi + 1] = 0.0f;
                out[OUT_SC + gi] = NEG_INF;
                out[OUT_VALID + gi] = 0.0f;
            }
            float* drow = out + OUT_D + (size_t)gi * D;
            drow[lane] = 0.0f;
            drow[lane + 32] = 0.0f;
            drow[lane + 64] = 0.0f;
            drow[lane + 96] = 0.0f;
        }
    }

    // ========== tail: last block to finish re-zeros ALL state for next replay ===
    __syncthreads();
    if (tid == 0) {
        __threadfence();
        slast = (atomicAdd(&g_done, 1u) == NB - 1) ? 1 : 0;
    }
    __syncthreads();
    if (slast) {
        unsigned int* h1 = &g_hist1[0][0];
        for (int i = tid; i < NH * 2048; i += NT) h1[i] = 0u;
        for (int i = tid; i < 2048; i += NT) g_hist2[i] = 0u;
        __syncthreads();
        if (tid == 0) { g_ncand = 0; g_nsel = 0; __threadfence(); g_done = 0u; }
    }
}

// ---------------- launch ---------------------------------------------------------
extern "C" void kernel_launch(void* const* d_in, const int* in_sizes, int n_in,
                              void* d_out, int out_size) {
    const float* feat = (const float*)d_in[0];
    const int* ow_p = (n_in > 1) ? (const int*)d_in[1] : nullptr;
    const int* oh_p = (n_in > 2) ? (const int*)d_in[2] : nullptr;
    float* out = (float*)d_out;
    cudaFuncSetAttribute(disk_mega, cudaFuncAttributeMaxDynamicSharedMemorySize,
                         (int)sizeof(SmU));
    disk_mega<<<NB, NT, sizeof(SmU)>>>(feat, ow_p, oh_p, out);
}

// round 14
// speedup vs baseline: 1.5869x; 1.0470x over previous
#include <cuda_runtime.h>
#include <cstdint>

#define H 1024
#define W 1024
#define D 128
#define K 2048
#define SELCAP 4096
#define NB 128            // blocks == number of detect tiles; all co-resident
#define NT 1024
#define NH 8              // replicated hist1 copies
#define NEG_INF __int_as_float(0xFF800000)

// detect tiling: 128(w) x 64(h) output tiles, 8 x 16 = 128 tiles, ONE per block
#define TSX 128
#define TSY 64
#define HALO_ROWS (TSY + 4)        // 68
#define HALO_F4 ((TSX + 8) / 4)    // 34 float4 per row
#define HALO_TASKS (HALO_ROWS * HALO_F4)   // 2312
#define TILE_PITCH 140             // 136 used + pad (multiple of 4 floats)
#define RM_PITCH 132               // 128 used + pad (multiple of 4 floats)

// Output layout (float32): keypoints[K,2] | scores[K] | d[K,D] | valid[K]
#define OUT_KP 0
#define OUT_SC (K * 2)
#define OUT_D (K * 2 + K)
#define OUT_VALID (K * 2 + K + K * D)

// ---------------- scratch (static device globals; no allocation) ----------------
__device__ unsigned long long g_sel[SELCAP];
__device__ int g_nsel;
__device__ unsigned int g_hist1[NH][2048];
__device__ unsigned int g_hist2[2048];
__device__ unsigned int g_barcnt;
__device__ volatile unsigned int g_bargen;
__device__ unsigned int g_done;

// ---------------- dynamic shared memory layout ----------------------------------
// det region is dead by the time scan/rank regions are used; list survives all.
struct __align__(16) SmLayout {
    union {
        struct {
            float tile[HALO_ROWS][TILE_PITCH];    // 68*140*4 = 38080 B
            float rowmax[HALO_ROWS][RM_PITCH];    // 68*132*4 = 35904 B
        } det;                                    // 73984 B total
        struct {
            unsigned int s[2048];                 // 8 KB  (scan)
            unsigned long long keys[SELCAP];      // 32 KB (rank)
        } sr;
    } u;
    unsigned long long list[1024];                // block-local candidates
    int cnt;
};

// ---------------- software grid barrier (all NB blocks resident) ----------------
__device__ __forceinline__ void gbar() {
    __syncthreads();
    if (threadIdx.x == 0) {
        unsigned int gen = g_bargen;
        __threadfence();
        if (atomicAdd(&g_barcnt, 1u) == NB - 1) {
            g_barcnt = 0;
            __threadfence();
            g_bargen = gen + 1;
        } else {
            while (g_bargen == gen) { }
        }
        __threadfence();
    }
    __syncthreads();
}

__device__ __forceinline__ void suffix_scan_2048(unsigned int* s, int tid) {
    for (int off = 1; off < 2048; off <<= 1) {
        unsigned int a0 = (tid + off < 2048) ? s[tid + off] : 0u;
        unsigned int a1 = (tid + 1024 + off < 2048) ? s[tid + 1024 + off] : 0u;
        __syncthreads();
        s[tid] += a0;
        s[tid + 1024] += a1;
        __syncthreads();
    }
}

__device__ __forceinline__ float fmax5(float a, float b, float c, float d, float e) {
    return fmaxf(fmaxf(fmaxf(a, b), fmaxf(c, d)), e);
}

__global__ __launch_bounds__(NT, 1) void disk_mega(const float* __restrict__ feat,
                                                   const int* __restrict__ ow_p,
                                                   const int* __restrict__ oh_p,
                                                   float* __restrict__ out) {
    extern __shared__ char smem_raw[];
    SmLayout& sm = *reinterpret_cast<SmLayout*>(smem_raw);
    __shared__ unsigned int sb1, sabove1, scnt1, stmin;
    __shared__ int slast;
    const unsigned int F = 0xFFFFFFFFu;
    const int tid = threadIdx.x;
    const int lane = tid & 31;
    const int wid = tid >> 5;
    const float* heat = feat + (size_t)D * H * W;
    const int ow = ow_p ? __ldg(ow_p) : W;
    const int oh = oh_p ? __ldg(oh_p) : H;

    // ========== phase 1: NMS detect, ONE 128x64 tile per block, vectorized ======
    {
        const int t = blockIdx.x;
        const int bx = (t & 7) * TSX, by = (t >> 3) * TSY;
        const int hc = blockIdx.x & (NH - 1);

        // halo load (float4, one MLP batch)
#pragma unroll
        for (int k = 0; k < 3; k++) {
            const int i = tid + k * NT;
            if (i < HALO_TASKS) {
                const int r = i / HALO_F4, c = i - r * HALO_F4;
                const int gy = by - 2 + r;
                const int gx0 = bx - 4 + c * 4;
                float4 v;
                if (gy >= 0 && gy < H && gx0 >= 0 && gx0 <= W - 4)
                    v = *(const float4*)(heat + (size_t)gy * W + gx0);
                else
                    v = make_float4(NEG_INF, NEG_INF, NEG_INF, NEG_INF);
                *(float4*)&sm.u.det.tile[r][c * 4] = v;
            }
        }
        if (tid == 0) sm.cnt = 0;
        __syncthreads();
        // horizontal 5-max, 4 outputs per task: 68 rows x 32 col-groups = 2176
#pragma unroll
        for (int k = 0; k < 3; k++) {
            const int i = tid + k * NT;
            if (i < HALO_ROWS * (TSX / 4)) {
                const int ty = i >> 5, g4 = (i & 31) * 4;
                const float4 a = *(const float4*)&sm.u.det.tile[ty][g4];
                const float4 b = *(const float4*)&sm.u.det.tile[ty][g4 + 4];
                const float4 c = *(const float4*)&sm.u.det.tile[ty][g4 + 8];
                float4 o;
                o.x = fmax5(a.z, a.w, b.x, b.y, b.z);
                o.y = fmax5(a.w, b.x, b.y, b.z, b.w);
                o.z = fmax5(b.x, b.y, b.z, b.w, c.x);
                o.w = fmax5(b.y, b.z, b.w, c.x, c.y);
                *(float4*)&sm.u.det.rowmax[ty][g4] = o;
            }
        }
        __syncthreads();
        // vertical 5-max + candidate test, 4 outputs per task: 64 x 32 = 2048
#pragma unroll
        for (int k = 0; k < 2; k++) {
            const int i = tid + k * NT;
            const int oy = i >> 5, g4 = (i & 31) * 4;
            const float4 r0 = *(const float4*)&sm.u.det.rowmax[oy][g4];
            const float4 r1 = *(const float4*)&sm.u.det.rowmax[oy + 1][g4];
            const float4 r2 = *(const float4*)&sm.u.det.rowmax[oy + 2][g4];
            const float4 r3 = *(const float4*)&sm.u.det.rowmax[oy + 3][g4];
            const float4 r4 = *(const float4*)&sm.u.det.rowmax[oy + 4][g4];
            const float4 cv = *(const float4*)&sm.u.det.tile[oy + 2][g4 + 4];
            float4 m;
            m.x = fmax5(r0.x, r1.x, r2.x, r3.x, r4.x);
            m.y = fmax5(r0.y, r1.y, r2.y, r3.y, r4.y);
            m.z = fmax5(r0.z, r1.z, r2.z, r3.z, r4.z);
            m.w = fmax5(r0.w, r1.w, r2.w, r3.w, r4.w);
            const int y = by + oy;
            const float vv[4] = {cv.x, cv.y, cv.z, cv.w};
            const float mm[4] = {m.x, m.y, m.z, m.w};
#pragma unroll
            for (int j = 0; j < 4; j++) {
                const int x = bx + g4 + j;
                const float v = vv[j];
                if (v > 0.0f && v == mm[j] && x <= ow - 1 && y <= oh - 1) {
                    const unsigned int uk = __float_as_uint(v) | 0x80000000u;
                    const unsigned int idx = (unsigned int)(y * W + x);
                    const int p = atomicAdd(&sm.cnt, 1);
                    sm.list[p] = ((unsigned long long)uk << 32) | (0xFFFFFFFFu - idx);
                    atomicAdd(&g_hist1[hc][uk >> 21], 1u);
                }
            }
        }
    }
    gbar();

    // ========== phase 2: scan1 -> b1; fast-path threshold or level-2 refine =====
    unsigned int tmin;
    {
        unsigned int a0 = 0u, a1 = 0u;
#pragma unroll
        for (int c = 0; c < NH; c++) {
            a0 += __ldcg(&g_hist1[c][tid]);
            a1 += __ldcg(&g_hist1[c][tid + 1024]);
        }
        sm.u.sr.s[tid] = a0;
        sm.u.sr.s[tid + 1024] = a1;
        __syncthreads();
        suffix_scan_2048(sm.u.sr.s, tid);
        for (int b = tid; b < 2048; b += NT) {
            if (sm.u.sr.s[b] >= K && (b == 2047 || sm.u.sr.s[b + 1] < K)) {
                sb1 = (unsigned int)b;
                sabove1 = (b < 2047) ? sm.u.sr.s[b + 1] : 0u;
                scnt1 = sm.u.sr.s[b];
            }
        }
        if (tid == 0 && sm.u.sr.s[0] < K) { sb1 = 0u; sabove1 = 0u; scnt1 = sm.u.sr.s[0]; }
        __syncthreads();
        const unsigned int b1 = sb1;
        const unsigned int above1 = sabove1;
        const bool fast = (scnt1 <= SELCAP);   // uniform across blocks (same data)
        if (fast) {
            tmin = b1 << 21;   // whole boundary bin fits in SELCAP
        } else {
            // level-2 refinement using block-local candidate lists
            const int cnt = sm.cnt;
            if (tid < cnt) {
                const unsigned int hi = (unsigned int)(sm.list[tid] >> 32);
                if ((hi >> 21) == b1) atomicAdd(&g_hist2[(hi >> 10) & 0x7FFu], 1u);
            }
            gbar();
            sm.u.sr.s[tid] = __ldcg(&g_hist2[tid]);
            sm.u.sr.s[tid + 1024] = __ldcg(&g_hist2[tid + 1024]);
            __syncthreads();
            suffix_scan_2048(sm.u.sr.s, tid);
            for (int b = tid; b < 2048; b += NT) {
                if (above1 + sm.u.sr.s[b] >= K &&
                    (b == 2047 || above1 + sm.u.sr.s[b + 1] < K)) {
                    stmin = (b1 << 21) | ((unsigned int)b << 10);
                }
            }
            if (tid == 0 && above1 + sm.u.sr.s[0] < K) stmin = (b1 << 21);
            __syncthreads();
            tmin = stmin;
        }
    }

    // ========== phase 3: filter own smem list -> g_sel (single pass) ============
    {
        const int cnt = sm.cnt;        // <= 1024 by construction (max ~946)
        unsigned long long key = 0ull;
        bool keep = false;
        if (tid < cnt) {
            key = sm.list[tid];
            keep = ((unsigned int)(key >> 32)) >= tmin;
        }
        const unsigned int mask = __ballot_sync(F, keep);
        if (mask) {
            const int leader = __ffs(mask) - 1;
            int base = 0;
            if (lane == leader) base = atomicAdd(&g_nsel, __popc(mask));
            base = __shfl_sync(F, base, leader);
            if (keep) {
                const int off = __popc(mask & ((1u << lane) - 1u));
                if (base + off < SELCAP) g_sel[base + off] = key;
            }
        }
    }
    gbar();

    // ========== phase 4: rank (one warp/survivor) + emit + fused gather =========
    {
        const int nsel = min(__ldcg(&g_nsel), SELCAP);
        for (int i = tid; i < nsel; i += NT) sm.u.sr.keys[i] = __ldcg(&g_sel[i]);
        __syncthreads();
        const int gi = wid * NB + blockIdx.x;  // strided: spreads gather over blocks
        if (gi < nsel) {
            const unsigned long long key = sm.u.sr.keys[gi];
            unsigned int r = 0;
            for (int j = lane; j < nsel; j += 32)
                r += (sm.u.sr.keys[j] > key) ? 1u : 0u;
            r = __reduce_add_sync(F, r);   // exact rank, keys unique
            if (r < K) {
                const unsigned int hi = (unsigned int)(key >> 32);
                const unsigned int idx = 0xFFFFFFFFu - (unsigned int)key;
                if (lane == 0) {
                    out[OUT_KP + 2 * r + 0] = (float)(idx & (W - 1));
                    out[OUT_KP + 2 * r + 1] = (float)(idx >> 10);
                    out[OUT_SC + r] = __uint_as_float(hi & 0x7FFFFFFFu);
                    out[OUT_VALID + r] = 1.0f;
                }
                // fused descriptor gather + L2 normalize (4 channels per lane)
                float v0 = __ldg(&feat[(size_t)(lane)*(H * W) + idx]);
                float v1 = __ldg(&feat[(size_t)(lane + 32) * (H * W) + idx]);
                float v2 = __ldg(&feat[(size_t)(lane + 64) * (H * W) + idx]);
                float v3 = __ldg(&feat[(size_t)(lane + 96) * (H * W) + idx]);
                float ss = v0 * v0 + v1 * v1 + v2 * v2 + v3 * v3;
#pragma unroll
                for (int o = 16; o > 0; o >>= 1)
                    ss += __shfl_xor_sync(F, ss, o);
                const float inorm = 1.0f / fmaxf(sqrtf(ss), 1e-12f);
                float* drow = out + OUT_D + (size_t)r * D;
                drow[lane] = v0 * inorm;
                drow[lane + 32] = v1 * inorm;
                drow[lane + 64] = v2 * inorm;
                drow[lane + 96] = v3 * inorm;
            }
        } else if (gi < K) {  // padding rows when nsel < K (rows nsel..K-1)
            if (lane == 0) {
                out[OUT_KP + 2 * gi + 0] = 0.0f;
                out[OUT_KP + 2 * gi + 1] = 0.0f;
                out[OUT_SC + gi] = NEG_INF;
                out[OUT_VALID + gi] = 0.0f;
            }
            float* drow = out + OUT_D + (size_t)gi * D;
            drow[lane] = 0.0f;
            drow[lane + 32] = 0.0f;
            drow[lane + 64] = 0.0f;
            drow[lane + 96] = 0.0f;
        }
    }

    // ========== tail: last block to finish re-zeros ALL state for next replay ===
    __syncthreads();
    if (tid == 0) {
        __threadfence();
        slast = (atomicAdd(&g_done, 1u) == NB - 1) ? 1 : 0;
    }
    __syncthreads();
    if (slast) {
        unsigned int* h1 = &g_hist1[0][0];
        for (int i = tid; i < NH * 2048; i += NT) h1[i] = 0u;
        for (int i = tid; i < 2048; i += NT) g_hist2[i] = 0u;
        __syncthreads();
        if (tid == 0) { g_nsel = 0; __threadfence(); g_done = 0u; }
    }
}

// ---------------- launch ---------------------------------------------------------
extern "C" void kernel_launch(void* const* d_in, const int* in_sizes, int n_in,
                              void* d_out, int out_size) {
    const float* feat = (const float*)d_in[0];
    const int* ow_p = (n_in > 1) ? (const int*)d_in[1] : nullptr;
    const int* oh_p = (n_in > 2) ? (const int*)d_in[2] : nullptr;
    float* out = (float*)d_out;
    cudaFuncSetAttribute(disk_mega, cudaFuncAttributeMaxDynamicSharedMemorySize,
                         (int)sizeof(SmLayout));
    disk_mega<<<NB, NT, sizeof(SmLayout)>>>(feat, ow_p, oh_p, out);
}

// round 15
// speedup vs baseline: 1.6268x; 1.0252x over previous
#include <cuda_runtime.h>
#include <cstdint>

#define H 1024
#define W 1024
#define D 128
#define K 2048
#define SELCAP 4096
#define NB 128            // blocks == number of detect tiles; all co-resident
#define NT 1024
#define NH 8              // replicated hist1 copies
#define NEG_INF __int_as_float(0xFF800000)

// detect tiling: 128(w) x 64(h) output tiles, 8 x 16 = 128 tiles, ONE per block
#define TSX 128
#define TSY 64
#define HALO_ROWS (TSY + 4)        // 68
#define HALO_F4 ((TSX + 8) / 4)    // 34 float4 per row
#define HALO_TASKS (HALO_ROWS * HALO_F4)   // 2312
#define TILE_PITCH 140
#define RM_PITCH 132

// Output layout (float32): keypoints[K,2] | scores[K] | d[K,D] | valid[K]
#define OUT_KP 0
#define OUT_SC (K * 2)
#define OUT_D (K * 2 + K)
#define OUT_VALID (K * 2 + K + K * D)

// ---------------- scratch (static device globals; no allocation) ----------------
__device__ unsigned long long g_sel[SELCAP];
__device__ int g_nsel;
__device__ unsigned int g_hist1[NH][2048];
__device__ unsigned int g_hist2[2048];
__device__ unsigned int g_barcnt;
__device__ volatile unsigned int g_bargen;
__device__ unsigned int g_done;

// ---------------- dynamic shared memory layout ----------------------------------
struct __align__(16) SmLayout {
    union {
        struct {
            float tile[HALO_ROWS][TILE_PITCH];
            float rowmax[HALO_ROWS][RM_PITCH];
        } det;
        struct {
            unsigned int s[2048];
            unsigned long long keys[SELCAP];
        } sr;
    } u;
    unsigned long long list[1024];   // block-local candidates (survives phases)
    int cnt;
};

// ---------------- software grid barrier (all NB blocks resident) ----------------
__device__ __forceinline__ void gbar() {
    __syncthreads();
    if (threadIdx.x == 0) {
        unsigned int gen = g_bargen;
        __threadfence();
        if (atomicAdd(&g_barcnt, 1u) == NB - 1) {
            g_barcnt = 0;
            __threadfence();
            g_bargen = gen + 1;
        } else {
            while (g_bargen == gen) { }
        }
        __threadfence();
    }
    __syncthreads();
}

// suffix scan of 2048 bins via reversed prefix scan; r0 = h[2047-2tid],
// r1 = h[2046-2tid]. Result: s[b] = sum_{j>=b} h[j]. 3 syncs total.
__device__ __forceinline__ void suffix_scan_fast(unsigned int* s, unsigned int* ws,
                                                 unsigned int r0, unsigned int r1,
                                                 int tid) {
    const unsigned int F = 0xFFFFFFFFu;
    const int lane = tid & 31, wid = tid >> 5;
    const unsigned int local = r0 + r1;
    unsigned int inc = local;
#pragma unroll
    for (int o = 1; o < 32; o <<= 1) {
        const unsigned int t = __shfl_up_sync(F, inc, o);
        if (lane >= o) inc += t;
    }
    if (lane == 31) ws[wid] = inc;
    __syncthreads();
    if (wid == 0) {
        const unsigned int w = ws[lane];
        unsigned int wi = w;
#pragma unroll
        for (int o = 1; o < 32; o <<= 1) {
            const unsigned int t = __shfl_up_sync(F, wi, o);
            if (lane >= o) wi += t;
        }
        ws[lane] = wi - w;   // exclusive warp offset
    }
    __syncthreads();
    const unsigned int base = ws[wid] + (inc - local);
    s[2047 - 2 * tid] = base + r0;
    s[2046 - 2 * tid] = base + r0 + r1;
    __syncthreads();
}

__device__ __forceinline__ float fmax5(float a, float b, float c, float d, float e) {
    return fmaxf(fmaxf(fmaxf(a, b), fmaxf(c, d)), e);
}

__global__ __launch_bounds__(NT, 1) void disk_mega(const float* __restrict__ feat,
                                                   const int* __restrict__ ow_p,
                                                   const int* __restrict__ oh_p,
                                                   float* __restrict__ out) {
    extern __shared__ char smem_raw[];
    SmLayout& sm = *reinterpret_cast<SmLayout*>(smem_raw);
    __shared__ unsigned int ws[32];
    __shared__ unsigned int sb1, sabove1, scnt1, stmin;
    __shared__ int slast;
    const unsigned int F = 0xFFFFFFFFu;
    const int tid = threadIdx.x;
    const int lane = tid & 31;
    const int wid = tid >> 5;
    const float* heat = feat + (size_t)D * H * W;
    const int ow = ow_p ? __ldg(ow_p) : W;
    const int oh = oh_p ? __ldg(oh_p) : H;

    // ========== phase 1: NMS detect, ONE 128x64 tile per block, vectorized ======
    {
        const int t = blockIdx.x;
        const int bx = (t & 7) * TSX, by = (t >> 3) * TSY;
        const int hc = blockIdx.x & (NH - 1);
#pragma unroll
        for (int k = 0; k < 3; k++) {
            const int i = tid + k * NT;
            if (i < HALO_TASKS) {
                const int r = i / HALO_F4, c = i - r * HALO_F4;
                const int gy = by - 2 + r;
                const int gx0 = bx - 4 + c * 4;
                float4 v;
                if (gy >= 0 && gy < H && gx0 >= 0 && gx0 <= W - 4)
                    v = *(const float4*)(heat + (size_t)gy * W + gx0);
                else
                    v = make_float4(NEG_INF, NEG_INF, NEG_INF, NEG_INF);
                *(float4*)&sm.u.det.tile[r][c * 4] = v;
            }
        }
        if (tid == 0) sm.cnt = 0;
        __syncthreads();
#pragma unroll
        for (int k = 0; k < 3; k++) {
            const int i = tid + k * NT;
            if (i < HALO_ROWS * (TSX / 4)) {
                const int ty = i >> 5, g4 = (i & 31) * 4;
                const float4 a = *(const float4*)&sm.u.det.tile[ty][g4];
                const float4 b = *(const float4*)&sm.u.det.tile[ty][g4 + 4];
                const float4 c = *(const float4*)&sm.u.det.tile[ty][g4 + 8];
                float4 o;
                o.x = fmax5(a.z, a.w, b.x, b.y, b.z);
                o.y = fmax5(a.w, b.x, b.y, b.z, b.w);
                o.z = fmax5(b.x, b.y, b.z, b.w, c.x);
                o.w = fmax5(b.y, b.z, b.w, c.x, c.y);
                *(float4*)&sm.u.det.rowmax[ty][g4] = o;
            }
        }
        __syncthreads();
#pragma unroll
        for (int k = 0; k < 2; k++) {
            const int i = tid + k * NT;
            const int oy = i >> 5, g4 = (i & 31) * 4;
            const float4 r0 = *(const float4*)&sm.u.det.rowmax[oy][g4];
            const float4 r1 = *(const float4*)&sm.u.det.rowmax[oy + 1][g4];
            const float4 r2 = *(const float4*)&sm.u.det.rowmax[oy + 2][g4];
            const float4 r3 = *(const float4*)&sm.u.det.rowmax[oy + 3][g4];
            const float4 r4 = *(const float4*)&sm.u.det.rowmax[oy + 4][g4];
            const float4 cv = *(const float4*)&sm.u.det.tile[oy + 2][g4 + 4];
            float4 m;
            m.x = fmax5(r0.x, r1.x, r2.x, r3.x, r4.x);
            m.y = fmax5(r0.y, r1.y, r2.y, r3.y, r4.y);
            m.z = fmax5(r0.z, r1.z, r2.z, r3.z, r4.z);
            m.w = fmax5(r0.w, r1.w, r2.w, r3.w, r4.w);
            const int y = by + oy;
            const float vv[4] = {cv.x, cv.y, cv.z, cv.w};
            const float mm[4] = {m.x, m.y, m.z, m.w};
#pragma unroll
            for (int j = 0; j < 4; j++) {
                const int x = bx + g4 + j;
                const float v = vv[j];
                if (v > 0.0f && v == mm[j] && x <= ow - 1 && y <= oh - 1) {
                    const unsigned int uk = __float_as_uint(v) | 0x80000000u;
                    const unsigned int idx = (unsigned int)(y * W + x);
                    const int p = atomicAdd(&sm.cnt, 1);
                    sm.list[p] = ((unsigned long long)uk << 32) | (0xFFFFFFFFu - idx);
                    atomicAdd(&g_hist1[hc][uk >> 21], 1u);
                }
            }
        }
    }
    gbar();

    // ========== phase 2: fast scan1 -> b1; fast-path threshold or refine ========
    unsigned int tmin;
    {
        unsigned int a0 = 0u, a1 = 0u;   // a0 = h[2047-2tid], a1 = h[2046-2tid]
#pragma unroll
        for (int c = 0; c < NH; c++) {
            const uint2 h2 = __ldcg(&((const uint2*)g_hist1[c])[1023 - tid]);
            a0 += h2.y;
            a1 += h2.x;
        }
        suffix_scan_fast(sm.u.sr.s, ws, a0, a1, tid);
        for (int b = tid; b < 2048; b += NT) {
            if (sm.u.sr.s[b] >= K && (b == 2047 || sm.u.sr.s[b + 1] < K)) {
                sb1 = (unsigned int)b;
                sabove1 = (b < 2047) ? sm.u.sr.s[b + 1] : 0u;
                scnt1 = sm.u.sr.s[b];
            }
        }
        if (tid == 0 && sm.u.sr.s[0] < K) { sb1 = 0u; sabove1 = 0u; scnt1 = sm.u.sr.s[0]; }
        __syncthreads();
        const unsigned int b1 = sb1;
        const unsigned int above1 = sabove1;
        const bool fast = (scnt1 <= SELCAP);   // uniform across blocks (same data)
        if (fast) {
            tmin = b1 << 21;
        } else {
            const int cnt = sm.cnt;
            if (tid < cnt) {
                const unsigned int hi = (unsigned int)(sm.list[tid] >> 32);
                if ((hi >> 21) == b1) atomicAdd(&g_hist2[(hi >> 10) & 0x7FFu], 1u);
            }
            gbar();
            const uint2 h2 = __ldcg(&((const uint2*)g_hist2)[1023 - tid]);
            suffix_scan_fast(sm.u.sr.s, ws, h2.y, h2.x, tid);
            for (int b = tid; b < 2048; b += NT) {
                if (above1 + sm.u.sr.s[b] >= K &&
                    (b == 2047 || above1 + sm.u.sr.s[b + 1] < K)) {
                    stmin = (b1 << 21) | ((unsigned int)b << 10);
                }
            }
            if (tid == 0 && above1 + sm.u.sr.s[0] < K) stmin = (b1 << 21);
            __syncthreads();
            tmin = stmin;
        }
    }

    // ========== phase 3: filter own smem list -> g_sel (single pass) ============
    {
        const int cnt = sm.cnt;        // <= 1024 by construction (max ~946)
        unsigned long long key = 0ull;
        bool keep = false;
        if (tid < cnt) {
            key = sm.list[tid];
            keep = ((unsigned int)(key >> 32)) >= tmin;
        }
        const unsigned int mask = __ballot_sync(F, keep);
        if (mask) {
            const int leader = __ffs(mask) - 1;
            int base = 0;
            if (lane == leader) base = atomicAdd(&g_nsel, __popc(mask));
            base = __shfl_sync(F, base, leader);
            if (keep) {
                const int off = __popc(mask & ((1u << lane) - 1u));
                if (base + off < SELCAP) g_sel[base + off] = key;
            }
        }
    }
    gbar();

    // ========== phase 4: rank + fused gather (loads issued BEFORE rank) =========
    {
        const int nsel = min(__ldcg(&g_nsel), SELCAP);
        for (int i = tid; i < nsel; i += NT) sm.u.sr.keys[i] = __ldcg(&g_sel[i]);
        __syncthreads();
        const int gi = wid * NB + blockIdx.x;  // strided: spreads gather over blocks
        if (gi < nsel) {
            const unsigned long long key = sm.u.sr.keys[gi];
            const unsigned int hi = (unsigned int)(key >> 32);
            const unsigned int idx = 0xFFFFFFFFu - (unsigned int)key;
            // issue descriptor loads NOW; latency overlaps the rank loop below
            const float v0 = __ldg(&feat[(size_t)(lane)*(H * W) + idx]);
            const float v1 = __ldg(&feat[(size_t)(lane + 32) * (H * W) + idx]);
            const float v2 = __ldg(&feat[(size_t)(lane + 64) * (H * W) + idx]);
            const float v3 = __ldg(&feat[(size_t)(lane + 96) * (H * W) + idx]);
            unsigned int r = 0;
            for (int j = lane; j < nsel; j += 32)
                r += (sm.u.sr.keys[j] > key) ? 1u : 0u;
            r = __reduce_add_sync(F, r);   // exact rank, keys unique
            if (r < K) {
                if (lane == 0) {
                    out[OUT_KP + 2 * r + 0] = (float)(idx & (W - 1));
                    out[OUT_KP + 2 * r + 1] = (float)(idx >> 10);
                    out[OUT_SC + r] = __uint_as_float(hi & 0x7FFFFFFFu);
                    out[OUT_VALID + r] = 1.0f;
                }
                float ss = v0 * v0 + v1 * v1 + v2 * v2 + v3 * v3;
#pragma unroll
                for (int o = 16; o > 0; o >>= 1)
                    ss += __shfl_xor_sync(F, ss, o);
                const float inorm = 1.0f / fmaxf(sqrtf(ss), 1e-12f);
                float* drow = out + OUT_D + (size_t)r * D;
                drow[lane] = v0 * inorm;
                drow[lane + 32] = v1 * inorm;
                drow[lane + 64] = v2 * inorm;
                drow[lane + 96] = v3 * inorm;
            }
        } else if (gi < K) {  // padding rows when nsel < K (rows nsel..K-1)
            if (lane == 0) {
                out[OUT_KP + 2 * gi + 0] = 0.0f;
                out[OUT_KP + 2 * gi + 1] = 0.0f;
                out[OUT_SC + gi] = NEG_INF;
                out[OUT_VALID + gi] = 0.0f;
            }
            float* drow = out + OUT_D + (size_t)gi * D;
            drow[lane] = 0.0f;
            drow[lane + 32] = 0.0f;
            drow[lane + 64] = 0.0f;
            drow[lane + 96] = 0.0f;
        }
    }

    // ========== tail: last block to finish re-zeros ALL state for next replay ===
    __syncthreads();
    if (tid == 0) {
        __threadfence();
        slast = (atomicAdd(&g_done, 1u) == NB - 1) ? 1 : 0;
    }
    __syncthreads();
    if (slast) {
        unsigned int* h1 = &g_hist1[0][0];
        for (int i = tid; i < NH * 2048; i += NT) h1[i] = 0u;
        for (int i = tid; i < 2048; i += NT) g_hist2[i] = 0u;
        __syncthreads();
        if (tid == 0) { g_nsel = 0; __threadfence(); g_done = 0u; }
    }
}

// ---------------- launch ---------------------------------------------------------
extern "C" void kernel_launch(void* const* d_in, const int* in_sizes, int n_in,
                              void* d_out, int out_size) {
    const float* feat = (const float*)d_in[0];
    const int* ow_p = (n_in > 1) ? (const int*)d_in[1] : nullptr;
    const int* oh_p = (n_in > 2) ? (const int*)d_in[2] : nullptr;
    float* out = (float*)d_out;
    cudaFuncSetAttribute(disk_mega, cudaFuncAttributeMaxDynamicSharedMemorySize,
                         (int)sizeof(SmLayout));
    disk_mega<<<NB, NT, sizeof(SmLayout)>>>(feat, ow_p, oh_p, out);
}

// round 16
// speedup vs baseline: 1.8131x; 1.1145x over previous
#include <cuda_runtime.h>
#include <cstdint>

#define H 1024
#define W 1024
#define D 128
#define K 2048
#define SELCAP 4096
#define NB 128            // blocks == number of detect tiles; all co-resident
#define NT 1024
#define NEG_INF __int_as_float(0xFF800000)

// detect tiling: 128(w) x 64(h) output tiles, 8 x 16 = 128 tiles, ONE per block
#define TSX 128
#define TSY 64
#define HALO_ROWS (TSY + 4)        // 68
#define HALO_F4 ((TSX + 8) / 4)    // 34 float4 per row
#define HALO_TASKS (HALO_ROWS * HALO_F4)   // 2312
#define TILE_PITCH 140
#define RM_PITCH 132

// Output layout (float32): keypoints[K,2] | scores[K] | d[K,D] | valid[K]
#define OUT_KP 0
#define OUT_SC (K * 2)
#define OUT_D (K * 2 + K)
#define OUT_VALID (K * 2 + K + K * D)

// ---------------- scratch (static device globals; no allocation) ----------------
__device__ unsigned long long g_sel[SELCAP];
__device__ int g_nsel;
__device__ unsigned int g_hist1[2048];
__device__ unsigned int g_hist2[2048];
__device__ unsigned int g_barcnt;
__device__ volatile unsigned int g_bargen;
__device__ unsigned int g_done;

// ---------------- dynamic shared memory layout ----------------------------------
struct __align__(16) SmLayout {
    union {
        struct {
            float tile[HALO_ROWS][TILE_PITCH];
            float rowmax[HALO_ROWS][RM_PITCH];
            unsigned int hist[2048];          // block-local histogram
        } det;
        struct {
            unsigned int s[2048];
            unsigned long long keys[SELCAP];
        } sr;
    } u;
    unsigned long long list[1024];   // block-local candidates (survives phases)
    int cnt;
};

// ---------------- software grid barrier (all NB blocks resident) ----------------
__device__ __forceinline__ void gbar() {
    __syncthreads();
    if (threadIdx.x == 0) {
        unsigned int gen = g_bargen;
        __threadfence();
        if (atomicAdd(&g_barcnt, 1u) == NB - 1) {
            g_barcnt = 0;
            __threadfence();
            g_bargen = gen + 1;
        } else {
            while (g_bargen == gen) { }
        }
        __threadfence();
    }
    __syncthreads();
}

// suffix scan of 2048 bins via reversed prefix scan; r0 = h[2047-2tid],
// r1 = h[2046-2tid]. Result: s[b] = sum_{j>=b} h[j]. 3 syncs total.
__device__ __forceinline__ void suffix_scan_fast(unsigned int* s, unsigned int* ws,
                                                 unsigned int r0, unsigned int r1,
                                                 int tid) {
    const unsigned int F = 0xFFFFFFFFu;
    const int lane = tid & 31, wid = tid >> 5;
    const unsigned int local = r0 + r1;
    unsigned int inc = local;
#pragma unroll
    for (int o = 1; o < 32; o <<= 1) {
        const unsigned int t = __shfl_up_sync(F, inc, o);
        if (lane >= o) inc += t;
    }
    if (lane == 31) ws[wid] = inc;
    __syncthreads();
    if (wid == 0) {
        const unsigned int w = ws[lane];
        unsigned int wi = w;
#pragma unroll
        for (int o = 1; o < 32; o <<= 1) {
            const unsigned int t = __shfl_up_sync(F, wi, o);
            if (lane >= o) wi += t;
        }
        ws[lane] = wi - w;   // exclusive warp offset
    }
    __syncthreads();
    const unsigned int base = ws[wid] + (inc - local);
    s[2047 - 2 * tid] = base + r0;
    s[2046 - 2 * tid] = base + r0 + r1;
    __syncthreads();
}

__device__ __forceinline__ float fmax5(float a, float b, float c, float d, float e) {
    return fmaxf(fmaxf(fmaxf(a, b), fmaxf(c, d)), e);
}

__global__ __launch_bounds__(NT, 1) void disk_mega(const float* __restrict__ feat,
                                                   const int* __restrict__ ow_p,
                                                   const int* __restrict__ oh_p,
                                                   float* __restrict__ out) {
    extern __shared__ char smem_raw[];
    SmLayout& sm = *reinterpret_cast<SmLayout*>(smem_raw);
    __shared__ unsigned int ws[32];
    __shared__ unsigned int sb1, sabove1, scnt1, stmin;
    __shared__ int slast;
    const unsigned int F = 0xFFFFFFFFu;
    const int tid = threadIdx.x;
    const int lane = tid & 31;
    const int wid = tid >> 5;
    const float* heat = feat + (size_t)D * H * W;
    const int ow = ow_p ? __ldg(ow_p) : W;
    const int oh = oh_p ? __ldg(oh_p) : H;

    // ========== phase 1: NMS detect, ONE 128x64 tile per block ==================
    {
        const int t = blockIdx.x;
        const int bx = (t & 7) * TSX, by = (t >> 3) * TSY;
        // zero block-local histogram
        sm.u.det.hist[tid] = 0u;
        sm.u.det.hist[tid + 1024] = 0u;
        // halo load (float4, one MLP batch)
#pragma unroll
        for (int k = 0; k < 3; k++) {
            const int i = tid + k * NT;
            if (i < HALO_TASKS) {
                const int r = i / HALO_F4, c = i - r * HALO_F4;
                const int gy = by - 2 + r;
                const int gx0 = bx - 4 + c * 4;
                float4 v;
                if (gy >= 0 && gy < H && gx0 >= 0 && gx0 <= W - 4)
                    v = *(const float4*)(heat + (size_t)gy * W + gx0);
                else
                    v = make_float4(NEG_INF, NEG_INF, NEG_INF, NEG_INF);
                *(float4*)&sm.u.det.tile[r][c * 4] = v;
            }
        }
        if (tid == 0) sm.cnt = 0;
        __syncthreads();
        // horizontal 5-max (float4)
#pragma unroll
        for (int k = 0; k < 3; k++) {
            const int i = tid + k * NT;
            if (i < HALO_ROWS * (TSX / 4)) {
                const int ty = i >> 5, g4 = (i & 31) * 4;
                const float4 a = *(const float4*)&sm.u.det.tile[ty][g4];
                const float4 b = *(const float4*)&sm.u.det.tile[ty][g4 + 4];
                const float4 c = *(const float4*)&sm.u.det.tile[ty][g4 + 8];
                float4 o;
                o.x = fmax5(a.z, a.w, b.x, b.y, b.z);
                o.y = fmax5(a.w, b.x, b.y, b.z, b.w);
                o.z = fmax5(b.x, b.y, b.z, b.w, c.x);
                o.w = fmax5(b.y, b.z, b.w, c.x, c.y);
                *(float4*)&sm.u.det.rowmax[ty][g4] = o;
            }
        }
        __syncthreads();
        // vertical 5-max + warp-aggregated candidate emission
#pragma unroll
        for (int k = 0; k < 2; k++) {
            const int i = tid + k * NT;
            const int oy = i >> 5, g4 = (i & 31) * 4;
            const float4 r0 = *(const float4*)&sm.u.det.rowmax[oy][g4];
            const float4 r1 = *(const float4*)&sm.u.det.rowmax[oy + 1][g4];
            const float4 r2 = *(const float4*)&sm.u.det.rowmax[oy + 2][g4];
            const float4 r3 = *(const float4*)&sm.u.det.rowmax[oy + 3][g4];
            const float4 r4 = *(const float4*)&sm.u.det.rowmax[oy + 4][g4];
            const float4 cv = *(const float4*)&sm.u.det.tile[oy + 2][g4 + 4];
            float4 m;
            m.x = fmax5(r0.x, r1.x, r2.x, r3.x, r4.x);
            m.y = fmax5(r0.y, r1.y, r2.y, r3.y, r4.y);
            m.z = fmax5(r0.z, r1.z, r2.z, r3.z, r4.z);
            m.w = fmax5(r0.w, r1.w, r2.w, r3.w, r4.w);
            const int y = by + oy;
            const float vv[4] = {cv.x, cv.y, cv.z, cv.w};
            const float mm[4] = {m.x, m.y, m.z, m.w};
#pragma unroll
            for (int j = 0; j < 4; j++) {
                const int x = bx + g4 + j;
                const float v = vv[j];
                const bool pred =
                    (v > 0.0f) && (v == mm[j]) && (x <= ow - 1) && (y <= oh - 1);
                const unsigned int mask = __ballot_sync(F, pred);
                if (mask) {
                    const int leader = __ffs(mask) - 1;
                    int base = 0;
                    if (lane == leader) base = atomicAdd(&sm.cnt, __popc(mask));
                    base = __shfl_sync(F, base, leader);
                    if (pred) {
                        const unsigned int uk = __float_as_uint(v) | 0x80000000u;
                        const unsigned int idx = (unsigned int)(y * W + x);
                        const int off = __popc(mask & ((1u << lane) - 1u));
                        sm.list[base + off] =
                            ((unsigned long long)uk << 32) | (0xFFFFFFFFu - idx);
                        atomicAdd(&sm.u.det.hist[uk >> 21], 1u);  // scattered bins
                    }
                }
            }
        }
        __syncthreads();
        // flush nonzero histogram bins to global (few dozen REDs per block)
#pragma unroll
        for (int k = 0; k < 2; k++) {
            const int b = tid + k * NT;
            const unsigned int hv = sm.u.det.hist[b];
            if (hv) atomicAdd(&g_hist1[b], hv);
        }
    }
    gbar();

    // ========== phase 2: fast scan1 -> b1; fast-path threshold or refine ========
    unsigned int tmin;
    {
        const uint2 h2 = __ldcg(&((const uint2*)g_hist1)[1023 - tid]);
        suffix_scan_fast(sm.u.sr.s, ws, h2.y, h2.x, tid);
        for (int b = tid; b < 2048; b += NT) {
            if (sm.u.sr.s[b] >= K && (b == 2047 || sm.u.sr.s[b + 1] < K)) {
                sb1 = (unsigned int)b;
                sabove1 = (b < 2047) ? sm.u.sr.s[b + 1] : 0u;
                scnt1 = sm.u.sr.s[b];
            }
        }
        if (tid == 0 && sm.u.sr.s[0] < K) { sb1 = 0u; sabove1 = 0u; scnt1 = sm.u.sr.s[0]; }
        __syncthreads();
        const unsigned int b1 = sb1;
        const unsigned int above1 = sabove1;
        const bool fast = (scnt1 <= SELCAP);   // uniform across blocks (same data)
        if (fast) {
            tmin = b1 << 21;
        } else {
            const int cnt = sm.cnt;
            if (tid < cnt) {
                const unsigned int hi = (unsigned int)(sm.list[tid] >> 32);
                if ((hi >> 21) == b1) atomicAdd(&g_hist2[(hi >> 10) & 0x7FFu], 1u);
            }
            gbar();
            const uint2 h2b = __ldcg(&((const uint2*)g_hist2)[1023 - tid]);
            suffix_scan_fast(sm.u.sr.s, ws, h2b.y, h2b.x, tid);
            for (int b = tid; b < 2048; b += NT) {
                if (above1 + sm.u.sr.s[b] >= K &&
                    (b == 2047 || above1 + sm.u.sr.s[b + 1] < K)) {
                    stmin = (b1 << 21) | ((unsigned int)b << 10);
                }
            }
            if (tid == 0 && above1 + sm.u.sr.s[0] < K) stmin = (b1 << 21);
            __syncthreads();
            tmin = stmin;
        }
    }

    // ========== phase 3: filter own smem list -> g_sel (single pass) ============
    {
        const int cnt = sm.cnt;        // <= 1024 by construction (max ~946)
        unsigned long long key = 0ull;
        bool keep = false;
        if (tid < cnt) {
            key = sm.list[tid];
            keep = ((unsigned int)(key >> 32)) >= tmin;
        }
        const unsigned int mask = __ballot_sync(F, keep);
        if (mask) {
            const int leader = __ffs(mask) - 1;
            int base = 0;
            if (lane == leader) base = atomicAdd(&g_nsel, __popc(mask));
            base = __shfl_sync(F, base, leader);
            if (keep) {
                const int off = __popc(mask & ((1u << lane) - 1u));
                if (base + off < SELCAP) g_sel[base + off] = key;
            }
        }
    }
    gbar();

    // ========== phase 4: rank + fused gather (loads issued BEFORE rank) =========
    {
        const int nsel = min(__ldcg(&g_nsel), SELCAP);
        for (int i = tid; i < nsel; i += NT) sm.u.sr.keys[i] = __ldcg(&g_sel[i]);
        __syncthreads();
        const int gi = wid * NB + blockIdx.x;  // strided: spreads gather over blocks
        if (gi < nsel) {
            const unsigned long long key = sm.u.sr.keys[gi];
            const unsigned int hi = (unsigned int)(key >> 32);
            const unsigned int idx = 0xFFFFFFFFu - (unsigned int)key;
            // issue descriptor loads NOW; latency overlaps the rank loop below
            const float v0 = __ldg(&feat[(size_t)(lane)*(H * W) + idx]);
            const float v1 = __ldg(&feat[(size_t)(lane + 32) * (H * W) + idx]);
            const float v2 = __ldg(&feat[(size_t)(lane + 64) * (H * W) + idx]);
            const float v3 = __ldg(&feat[(size_t)(lane + 96) * (H * W) + idx]);
            unsigned int r = 0;
            for (int j = lane; j < nsel; j += 32)
                r += (sm.u.sr.keys[j] > key) ? 1u : 0u;
            r = __reduce_add_sync(F, r);   // exact rank, keys unique
            if (r < K) {
                if (lane == 0) {
                    *(float2*)&out[OUT_KP + 2 * r] =
                        make_float2((float)(idx & (W - 1)), (float)(idx >> 10));
                    out[OUT_SC + r] = __uint_as_float(hi & 0x7FFFFFFFu);
                    out[OUT_VALID + r] = 1.0f;
                }
                float ss = v0 * v0 + v1 * v1 + v2 * v2 + v3 * v3;
#pragma unroll
                for (int o = 16; o > 0; o >>= 1)
                    ss += __shfl_xor_sync(F, ss, o);
                const float inorm = 1.0f / fmaxf(sqrtf(ss), 1e-12f);
                float* drow = out + OUT_D + (size_t)r * D;
                drow[lane] = v0 * inorm;
                drow[lane + 32] = v1 * inorm;
                drow[lane + 64] = v2 * inorm;
                drow[lane + 96] = v3 * inorm;
            }
        } else if (gi < K) {  // padding rows when nsel < K (rows nsel..K-1)
            if (lane == 0) {
                *(float2*)&out[OUT_KP + 2 * gi] = make_float2(0.0f, 0.0f);
                out[OUT_SC + gi] = NEG_INF;
                out[OUT_VALID + gi] = 0.0f;
            }
            float* drow = out + OUT_D + (size_t)gi * D;
            drow[lane] = 0.0f;
            drow[lane + 32] = 0.0f;
            drow[lane + 64] = 0.0f;
            drow[lane + 96] = 0.0f;
        }
    }

    // ========== tail: last block to finish re-zeros ALL state for next replay ===
    __syncthreads();
    if (tid == 0) {
        __threadfence();
        slast = (atomicAdd(&g_done, 1u) == NB - 1) ? 1 : 0;
    }
    __syncthreads();
    if (slast) {
        for (int i = tid; i < 2048; i += NT) {
            g_hist1[i] = 0u;
            g_hist2[i] = 0u;
        }
        __syncthreads();
        if (tid == 0) { g_nsel = 0; __threadfence(); g_done = 0u; }
    }
}

// ---------------- launch ---------------------------------------------------------
extern "C" void kernel_launch(void* const* d_in, const int* in_sizes, int n_in,
                              void* d_out, int out_size) {
    const float* feat = (const float*)d_in[0];
    const int* ow_p = (n_in > 1) ? (const int*)d_in[1] : nullptr;
    const int* oh_p = (n_in > 2) ? (const int*)d_in[2] : nullptr;
    float* out = (float*)d_out;
    cudaFuncSetAttribute(disk_mega, cudaFuncAttributeMaxDynamicSharedMemorySize,
                         (int)sizeof(SmLayout));
    disk_mega<<<NB, NT, sizeof(SmLayout)>>>(feat, ow_p, oh_p, out);
}